// round 1
// baseline (speedup 1.0000x reference)
#include <cuda_runtime.h>
#include <math.h>

#define B_  4
#define S_  2048
#define D_  1024
#define H_  16
#define HD_ 64

// Scratch (allocation-free rule: static __device__ arrays)
// g_qkv[part][((b*H+h)*S + s)*HD + hd], part: 0=Q 1=K 2=V   (3 x 32 MB)
__device__ float g_qkv[3][(size_t)B_ * H_ * S_ * HD_];
// attention context, laid out [B*S, D] for the proj GEMM       (32 MB)
__device__ float g_ctx[(size_t)B_ * S_ * D_];

// ---------------------------------------------------------------------------
// Kernel 1: QKV GEMM.  y[m,n] = sum_k x[m,k] * W[k,n] + b[n]
// M=8192 (B*S), N=3072 (3*D), K=1024.  128x128 tile, 8x8 per thread.
// Epilogue scatters into head-major Q/K/V.
// ---------------------------------------------------------------------------
__global__ __launch_bounds__(256) void qkv_gemm(const float* __restrict__ X,
                                                const float* __restrict__ W,
                                                const float* __restrict__ bias) {
    __shared__ float As[8][128];
    __shared__ float Bs[8][128];
    const int tid = threadIdx.x;
    const int tx = tid & 15, ty = tid >> 4;
    const int m0 = blockIdx.y * 128;
    const int n0 = blockIdx.x * 128;

    float acc[8][8];
#pragma unroll
    for (int i = 0; i < 8; i++)
#pragma unroll
        for (int j = 0; j < 8; j++) acc[i][j] = 0.f;

    const int a_row = tid >> 1;        // 0..127
    const int a_k4  = (tid & 1) * 4;   // 0 or 4
    const int b_row = tid >> 5;        // 0..7
    const int b_col = (tid & 31) * 4;  // 0..124

    const float* Xp = X + (size_t)(m0 + a_row) * 1024 + a_k4;
    const float* Wp = W + (size_t)b_row * 3072 + n0 + b_col;

    for (int kt = 0; kt < 1024; kt += 8) {
        float4 av = *(const float4*)(Xp + kt);
        As[a_k4 + 0][a_row] = av.x;
        As[a_k4 + 1][a_row] = av.y;
        As[a_k4 + 2][a_row] = av.z;
        As[a_k4 + 3][a_row] = av.w;
        *(float4*)&Bs[b_row][b_col] = *(const float4*)(Wp + (size_t)kt * 3072);
        __syncthreads();
#pragma unroll
        for (int kk = 0; kk < 8; kk++) {
            float a[8], b[8];
            *(float4*)(a)     = *(const float4*)&As[kk][ty * 8];
            *(float4*)(a + 4) = *(const float4*)&As[kk][ty * 8 + 4];
            *(float4*)(b)     = *(const float4*)&Bs[kk][tx * 8];
            *(float4*)(b + 4) = *(const float4*)&Bs[kk][tx * 8 + 4];
#pragma unroll
            for (int i = 0; i < 8; i++)
#pragma unroll
                for (int j = 0; j < 8; j++) acc[i][j] += a[i] * b[j];
        }
        __syncthreads();
    }

#pragma unroll
    for (int i = 0; i < 8; i++) {
        const int m = m0 + ty * 8 + i;
        const int bb = m >> 11;      // batch
        const int s  = m & 2047;     // seq pos
#pragma unroll
        for (int j = 0; j < 8; j++) {
            const int n = n0 + tx * 8 + j;
            const float v = acc[i][j] + bias[n];
            const int part = n >> 10;       // 0=q 1=k 2=v
            const int d1   = n & 1023;
            const int h  = d1 >> 6;
            const int hd = d1 & 63;
            g_qkv[part][((size_t)(bb * H_ + h) * S_ + s) * HD_ + hd] = v;
        }
    }
}

// ---------------------------------------------------------------------------
// Kernel 2: flash-style causal attention, fp32.
// Block = (b, h, q-tile of 64 rows). 256 threads = 16x16; each thread owns a
// 4x4 micro-tile of the 64x64 score block.  Online softmax with 16-lane
// butterfly reductions.  Dynamic smem: qs/ks/vs/ps, 64 x 68-float rows.
// ---------------------------------------------------------------------------
#define PAD_ 68
__global__ __launch_bounds__(256) void flash_attn() {
    extern __shared__ float sm[];
    float* qs = sm;                 // [d][r]  (Q^T, pre-scaled)
    float* ks = qs + 64 * PAD_;     // [d][c]  (K^T)
    float* vs = ks + 64 * PAD_;     // [k][c]
    float* ps = vs + 64 * PAD_;     // [r][k]

    const int tid = threadIdx.x;
    const int tx = tid & 15, ty = tid >> 4;
    const int q0 = blockIdx.x * 64;
    const int h  = blockIdx.y;
    const int b  = blockIdx.z;
    const float scale = 0.125f;  // 1/sqrt(64)

    const float* Q = g_qkv[0] + (size_t)(b * H_ + h) * S_ * HD_;
    const float* K = g_qkv[1] + (size_t)(b * H_ + h) * S_ * HD_;
    const float* V = g_qkv[2] + (size_t)(b * H_ + h) * S_ * HD_;

    for (int idx = tid; idx < 64 * 64; idx += 256) {
        const int r = idx >> 6, d = idx & 63;
        qs[d * PAD_ + r] = Q[(size_t)(q0 + r) * 64 + d] * scale;
    }

    const int r0 = ty * 4, c0 = tx * 4;
    float m_i[4], l_i[4], o[4][4];
#pragma unroll
    for (int i = 0; i < 4; i++) {
        m_i[i] = -1e30f;
        l_i[i] = 0.f;
#pragma unroll
        for (int j = 0; j < 4; j++) o[i][j] = 0.f;
    }
    __syncthreads();

    for (int j0 = 0; j0 <= q0; j0 += 64) {
        for (int idx = tid; idx < 64 * 64; idx += 256) {
            const int r = idx >> 6, d = idx & 63;
            ks[d * PAD_ + r] = K[(size_t)(j0 + r) * 64 + d];
        }
        for (int idx = tid; idx < 64 * 64; idx += 256) {
            const int k = idx >> 6, c = idx & 63;
            vs[k * PAD_ + c] = V[(size_t)(j0 + k) * 64 + c];
        }
        __syncthreads();

        // S = (Q*scale) @ K^T  (4x4 per thread)
        float s[4][4];
#pragma unroll
        for (int i = 0; i < 4; i++)
#pragma unroll
            for (int j = 0; j < 4; j++) s[i][j] = 0.f;
        for (int d = 0; d < 64; d++) {
            const float4 aq = *(const float4*)&qs[d * PAD_ + r0];
            const float4 bk = *(const float4*)&ks[d * PAD_ + c0];
            const float a[4] = {aq.x, aq.y, aq.z, aq.w};
            const float bb2[4] = {bk.x, bk.y, bk.z, bk.w};
#pragma unroll
            for (int i = 0; i < 4; i++)
#pragma unroll
                for (int j = 0; j < 4; j++) s[i][j] += a[i] * bb2[j];
        }

        if (j0 == q0) {  // diagonal tile: causal mask k > q
#pragma unroll
            for (int i = 0; i < 4; i++)
#pragma unroll
                for (int j = 0; j < 4; j++)
                    if (c0 + j > r0 + i) s[i][j] = -1e30f;
        }

        // online softmax update
#pragma unroll
        for (int i = 0; i < 4; i++) {
            float t = fmaxf(fmaxf(s[i][0], s[i][1]), fmaxf(s[i][2], s[i][3]));
#pragma unroll
            for (int off = 8; off; off >>= 1)
                t = fmaxf(t, __shfl_xor_sync(0xffffffffu, t, off));
            const float mn = fmaxf(m_i[i], t);
            const float fi = __expf(m_i[i] - mn);
            float sum = 0.f;
#pragma unroll
            for (int j = 0; j < 4; j++) {
                s[i][j] = __expf(s[i][j] - mn);
                sum += s[i][j];
            }
#pragma unroll
            for (int off = 8; off; off >>= 1)
                sum += __shfl_xor_sync(0xffffffffu, sum, off);
            l_i[i] = l_i[i] * fi + sum;
            m_i[i] = mn;
#pragma unroll
            for (int j = 0; j < 4; j++) o[i][j] *= fi;
        }

        // stage P to smem, then O += P @ V
#pragma unroll
        for (int i = 0; i < 4; i++)
#pragma unroll
            for (int j = 0; j < 4; j++) ps[(r0 + i) * PAD_ + c0 + j] = s[i][j];
        __syncthreads();

        for (int k = 0; k < 64; k++) {
            const float4 vv = *(const float4*)&vs[k * PAD_ + c0];
            const float vc[4] = {vv.x, vv.y, vv.z, vv.w};
            float pv[4];
#pragma unroll
            for (int i = 0; i < 4; i++) pv[i] = ps[(r0 + i) * PAD_ + k];
#pragma unroll
            for (int i = 0; i < 4; i++)
#pragma unroll
                for (int j = 0; j < 4; j++) o[i][j] += pv[i] * vc[j];
        }
        __syncthreads();
    }

#pragma unroll
    for (int i = 0; i < 4; i++) {
        const float inv = 1.f / l_i[i];
#pragma unroll
        for (int j = 0; j < 4; j++)
            g_ctx[(size_t)(b * S_ + q0 + r0 + i) * D_ + h * 64 + c0 + j] =
                o[i][j] * inv;
    }
}

// ---------------------------------------------------------------------------
// Kernel 3: output projection. out = ctx @ W_proj + b_proj
// M=8192, N=1024, K=1024.
// ---------------------------------------------------------------------------
__global__ __launch_bounds__(256) void proj_gemm(const float* __restrict__ W,
                                                 const float* __restrict__ bias,
                                                 float* __restrict__ out) {
    __shared__ float As[8][128];
    __shared__ float Bs[8][128];
    const int tid = threadIdx.x;
    const int tx = tid & 15, ty = tid >> 4;
    const int m0 = blockIdx.y * 128;
    const int n0 = blockIdx.x * 128;

    float acc[8][8];
#pragma unroll
    for (int i = 0; i < 8; i++)
#pragma unroll
        for (int j = 0; j < 8; j++) acc[i][j] = 0.f;

    const int a_row = tid >> 1;
    const int a_k4  = (tid & 1) * 4;
    const int b_row = tid >> 5;
    const int b_col = (tid & 31) * 4;

    const float* Xp = g_ctx + (size_t)(m0 + a_row) * 1024 + a_k4;
    const float* Wp = W + (size_t)b_row * 1024 + n0 + b_col;

    for (int kt = 0; kt < 1024; kt += 8) {
        float4 av = *(const float4*)(Xp + kt);
        As[a_k4 + 0][a_row] = av.x;
        As[a_k4 + 1][a_row] = av.y;
        As[a_k4 + 2][a_row] = av.z;
        As[a_k4 + 3][a_row] = av.w;
        *(float4*)&Bs[b_row][b_col] = *(const float4*)(Wp + (size_t)kt * 1024);
        __syncthreads();
#pragma unroll
        for (int kk = 0; kk < 8; kk++) {
            float a[8], b[8];
            *(float4*)(a)     = *(const float4*)&As[kk][ty * 8];
            *(float4*)(a + 4) = *(const float4*)&As[kk][ty * 8 + 4];
            *(float4*)(b)     = *(const float4*)&Bs[kk][tx * 8];
            *(float4*)(b + 4) = *(const float4*)&Bs[kk][tx * 8 + 4];
#pragma unroll
            for (int i = 0; i < 8; i++)
#pragma unroll
                for (int j = 0; j < 8; j++) acc[i][j] += a[i] * b[j];
        }
        __syncthreads();
    }

#pragma unroll
    for (int i = 0; i < 8; i++) {
        const int m = m0 + ty * 8 + i;
#pragma unroll
        for (int j = 0; j < 8; j++) {
            const int n = n0 + tx * 8 + j;
            out[(size_t)m * 1024 + n] = acc[i][j] + bias[n];
        }
    }
}

// ---------------------------------------------------------------------------
extern "C" void kernel_launch(void* const* d_in, const int* in_sizes, int n_in,
                              void* d_out, int out_size) {
    const float* x      = (const float*)d_in[0];
    const float* W_attn = (const float*)d_in[1];
    const float* b_attn = (const float*)d_in[2];
    const float* W_proj = (const float*)d_in[3];
    const float* b_proj = (const float*)d_in[4];
    float* out = (float*)d_out;

    const int flash_smem = 4 * 64 * PAD_ * (int)sizeof(float);  // 69632 B
    cudaFuncSetAttribute(flash_attn, cudaFuncAttributeMaxDynamicSharedMemorySize,
                         flash_smem);

    qkv_gemm<<<dim3(3072 / 128, 8192 / 128), 256>>>(x, W_attn, b_attn);
    flash_attn<<<dim3(S_ / 64, H_, B_), 256, flash_smem>>>();
    proj_gemm<<<dim3(1024 / 128, 8192 / 128), 256>>>(W_proj, b_proj, out);
}

// round 5
// speedup vs baseline: 1.5097x; 1.5097x over previous
#include <cuda_runtime.h>
#include <cuda_bf16.h>
#include <math.h>
#include <stdint.h>

#define B_  4
#define S_  2048
#define D_  1024
#define H_  16
#define HD_ 64

// Scratch (allocation-free rule: static __device__ arrays).
// IMPORTANT: referenced ONLY from device code, never passed as a host-side
// kernel argument (host shadow address bug broke R2-R4).
__device__ float g_qkv[3][(size_t)B_ * H_ * S_ * HD_];
__device__ float g_ctx[(size_t)B_ * S_ * D_];

// ---------------------------------------------------------------------------
// Tensor-core GEMM, bf16 2-term split: D = Ah@Bh + Ah@Bl + Al@Bh.
// Block tile 128x64, BK=16, 256 threads = 8 warps (4M x 2N),
// warp tile 32x32 = 2x4 m16n8k16 atoms -> acc = 32 floats/thread (low
// pressure; R1's passing kernel was 146 regs, this should be comparable).
// MODE 0: X = input x (arg), epilogue scatters into g_qkv.
// MODE 1: X = g_ctx (read via symbol in device code), epilogue writes out.
// ---------------------------------------------------------------------------

__device__ __forceinline__ uint32_t prmt_hi(uint32_t a, uint32_t b) {
    // d = { lo16 = a[31:16] (even k), hi16 = b[31:16] (odd k) }
    uint32_t d;
    asm("prmt.b32 %0, %1, %2, 0x7632;" : "=r"(d) : "r"(a), "r"(b));
    return d;
}
__device__ __forceinline__ uint32_t cvt_bf16x2(float hi_val, float lo_val) {
    uint32_t d;
    asm("cvt.rn.bf16x2.f32 %0, %1, %2;" : "=r"(d) : "f"(hi_val), "f"(lo_val));
    return d;
}
__device__ __forceinline__ void mma_bf16(float& c0, float& c1, float& c2, float& c3,
                                         uint32_t a0, uint32_t a1, uint32_t a2, uint32_t a3,
                                         uint32_t b0, uint32_t b1) {
    asm volatile(
        "mma.sync.aligned.m16n8k16.row.col.f32.bf16.bf16.f32 "
        "{%0,%1,%2,%3},{%4,%5,%6,%7},{%8,%9},{%0,%1,%2,%3};"
        : "+f"(c0), "+f"(c1), "+f"(c2), "+f"(c3)
        : "r"(a0), "r"(a1), "r"(a2), "r"(a3), "r"(b0), "r"(b1));
}

#define SROW 12  // smem row stride in uint32 words (8 k2 slots + 4 pad)

template <int LDN, int MODE>
__global__ __launch_bounds__(256) void tc_gemm(const float* __restrict__ Xarg,
                                               const float* __restrict__ W,
                                               const float* __restrict__ bias,
                                               float* __restrict__ out) {
    __shared__ uint32_t Ah[128 * SROW];   // 6144 B
    __shared__ uint32_t Al[128 * SROW];
    __shared__ uint32_t Bh[64 * SROW];    // 3072 B
    __shared__ uint32_t Bl[64 * SROW];

    const float* __restrict__ X = (MODE == 0) ? Xarg : (const float*)g_ctx;

    const int tid = threadIdx.x;
    const int lane = tid & 31;
    const int wid = tid >> 5;
    const int wm = wid >> 1;      // 0..3 : 32-row band
    const int wn = wid & 1;       // 0..1 : 32-col band
    const int grp = lane >> 2;    // 0..7
    const int tig = lane & 3;     // 0..3
    const int m0 = blockIdx.y * 128;
    const int n0 = blockIdx.x * 64;

    float acc[2][4][4];
#pragma unroll
    for (int mi = 0; mi < 2; mi++)
#pragma unroll
        for (int ni = 0; ni < 4; ni++)
#pragma unroll
            for (int r = 0; r < 4; r++) acc[mi][ni][r] = 0.f;

    // A loader: 2 float4 per thread (rows tid>>2 and +64, k2 base (tid&3)*2)
    const int am0 = tid >> 2;
    const int ak2 = (tid & 3) * 2;
    // B loader: threads 0..127, 2 float4 each (rows 2*bk2, 2*bk2+1; 4 cols)
    const int bk2 = tid & 7;
    const int bn4 = (tid >> 3) * 4;   // 0..60 for tid<128

    const int a_base = (wm * 32 + grp) * SROW + tig;
    const int b_base = (wn * 32 + grp) * SROW + tig;

#pragma unroll 1
    for (int kt = 0; kt < 1024; kt += 16) {
        // ---- A tile: X[m0..+127][kt..+15] -> Ah/Al ----
#pragma unroll
        for (int i = 0; i < 2; i++) {
            const int m = am0 + i * 64;
            const float4 v = *(const float4*)(X + (size_t)(m0 + m) * 1024 + kt + ak2 * 2);
            const uint32_t bx = __float_as_uint(v.x), by = __float_as_uint(v.y);
            const uint32_t bz = __float_as_uint(v.z), bw = __float_as_uint(v.w);
            Ah[m * SROW + ak2]     = prmt_hi(bx, by);
            Ah[m * SROW + ak2 + 1] = prmt_hi(bz, bw);
            const float lx = v.x - __uint_as_float(bx & 0xffff0000u);
            const float ly = v.y - __uint_as_float(by & 0xffff0000u);
            const float lz = v.z - __uint_as_float(bz & 0xffff0000u);
            const float lw = v.w - __uint_as_float(bw & 0xffff0000u);
            Al[m * SROW + ak2]     = cvt_bf16x2(ly, lx);
            Al[m * SROW + ak2 + 1] = cvt_bf16x2(lw, lz);
        }
        // ---- B tile: W[kt..+15][n0..+63] -> Bh/Bl (threads 0..127) ----
        if (tid < 128) {
            const float4 v0 = *(const float4*)(W + (size_t)(kt + 2 * bk2) * LDN + n0 + bn4);
            const float4 v1 = *(const float4*)(W + (size_t)(kt + 2 * bk2 + 1) * LDN + n0 + bn4);
            uint32_t be, bo;
            be = __float_as_uint(v0.x); bo = __float_as_uint(v1.x);
            Bh[(bn4 + 0) * SROW + bk2] = prmt_hi(be, bo);
            Bl[(bn4 + 0) * SROW + bk2] =
                cvt_bf16x2(v1.x - __uint_as_float(bo & 0xffff0000u),
                           v0.x - __uint_as_float(be & 0xffff0000u));
            be = __float_as_uint(v0.y); bo = __float_as_uint(v1.y);
            Bh[(bn4 + 1) * SROW + bk2] = prmt_hi(be, bo);
            Bl[(bn4 + 1) * SROW + bk2] =
                cvt_bf16x2(v1.y - __uint_as_float(bo & 0xffff0000u),
                           v0.y - __uint_as_float(be & 0xffff0000u));
            be = __float_as_uint(v0.z); bo = __float_as_uint(v1.z);
            Bh[(bn4 + 2) * SROW + bk2] = prmt_hi(be, bo);
            Bl[(bn4 + 2) * SROW + bk2] =
                cvt_bf16x2(v1.z - __uint_as_float(bo & 0xffff0000u),
                           v0.z - __uint_as_float(be & 0xffff0000u));
            be = __float_as_uint(v0.w); bo = __float_as_uint(v1.w);
            Bh[(bn4 + 3) * SROW + bk2] = prmt_hi(be, bo);
            Bl[(bn4 + 3) * SROW + bk2] =
                cvt_bf16x2(v1.w - __uint_as_float(bo & 0xffff0000u),
                           v0.w - __uint_as_float(be & 0xffff0000u));
        }
        __syncthreads();

        // ---- B fragments (16 regs) ----
        const uint32_t bh00 = Bh[b_base + 0 * 8 * SROW], bh01 = Bh[b_base + 0 * 8 * SROW + 4];
        const uint32_t bl00 = Bl[b_base + 0 * 8 * SROW], bl01 = Bl[b_base + 0 * 8 * SROW + 4];
        const uint32_t bh10 = Bh[b_base + 1 * 8 * SROW], bh11 = Bh[b_base + 1 * 8 * SROW + 4];
        const uint32_t bl10 = Bl[b_base + 1 * 8 * SROW], bl11 = Bl[b_base + 1 * 8 * SROW + 4];
        const uint32_t bh20 = Bh[b_base + 2 * 8 * SROW], bh21 = Bh[b_base + 2 * 8 * SROW + 4];
        const uint32_t bl20 = Bl[b_base + 2 * 8 * SROW], bl21 = Bl[b_base + 2 * 8 * SROW + 4];
        const uint32_t bh30 = Bh[b_base + 3 * 8 * SROW], bh31 = Bh[b_base + 3 * 8 * SROW + 4];
        const uint32_t bl30 = Bl[b_base + 3 * 8 * SROW], bl31 = Bl[b_base + 3 * 8 * SROW + 4];

#pragma unroll
        for (int mi = 0; mi < 2; mi++) {
            const int ab = a_base + mi * 16 * SROW;
            const uint32_t ah0 = Ah[ab];
            const uint32_t ah1 = Ah[ab + 8 * SROW];
            const uint32_t ah2 = Ah[ab + 4];
            const uint32_t ah3 = Ah[ab + 8 * SROW + 4];
            const uint32_t al0 = Al[ab];
            const uint32_t al1 = Al[ab + 8 * SROW];
            const uint32_t al2 = Al[ab + 4];
            const uint32_t al3 = Al[ab + 8 * SROW + 4];

            mma_bf16(acc[mi][0][0], acc[mi][0][1], acc[mi][0][2], acc[mi][0][3],
                     ah0, ah1, ah2, ah3, bh00, bh01);
            mma_bf16(acc[mi][0][0], acc[mi][0][1], acc[mi][0][2], acc[mi][0][3],
                     ah0, ah1, ah2, ah3, bl00, bl01);
            mma_bf16(acc[mi][0][0], acc[mi][0][1], acc[mi][0][2], acc[mi][0][3],
                     al0, al1, al2, al3, bh00, bh01);

            mma_bf16(acc[mi][1][0], acc[mi][1][1], acc[mi][1][2], acc[mi][1][3],
                     ah0, ah1, ah2, ah3, bh10, bh11);
            mma_bf16(acc[mi][1][0], acc[mi][1][1], acc[mi][1][2], acc[mi][1][3],
                     ah0, ah1, ah2, ah3, bl10, bl11);
            mma_bf16(acc[mi][1][0], acc[mi][1][1], acc[mi][1][2], acc[mi][1][3],
                     al0, al1, al2, al3, bh10, bh11);

            mma_bf16(acc[mi][2][0], acc[mi][2][1], acc[mi][2][2], acc[mi][2][3],
                     ah0, ah1, ah2, ah3, bh20, bh21);
            mma_bf16(acc[mi][2][0], acc[mi][2][1], acc[mi][2][2], acc[mi][2][3],
                     ah0, ah1, ah2, ah3, bl20, bl21);
            mma_bf16(acc[mi][2][0], acc[mi][2][1], acc[mi][2][2], acc[mi][2][3],
                     al0, al1, al2, al3, bh20, bh21);

            mma_bf16(acc[mi][3][0], acc[mi][3][1], acc[mi][3][2], acc[mi][3][3],
                     ah0, ah1, ah2, ah3, bh30, bh31);
            mma_bf16(acc[mi][3][0], acc[mi][3][1], acc[mi][3][2], acc[mi][3][3],
                     ah0, ah1, ah2, ah3, bl30, bl31);
            mma_bf16(acc[mi][3][0], acc[mi][3][1], acc[mi][3][2], acc[mi][3][3],
                     al0, al1, al2, al3, bh30, bh31);
        }
        __syncthreads();
    }

    // ---- epilogue ----
#pragma unroll
    for (int mi = 0; mi < 2; mi++) {
#pragma unroll
        for (int rr = 0; rr < 2; rr++) {
            const int row = m0 + wm * 32 + mi * 16 + grp + rr * 8;
#pragma unroll
            for (int ni = 0; ni < 4; ni++) {
                const int n = n0 + wn * 32 + ni * 8 + tig * 2;
                const float v0 = acc[mi][ni][rr * 2 + 0] + bias[n];
                const float v1 = acc[mi][ni][rr * 2 + 1] + bias[n + 1];
                if (MODE == 0) {
                    const int b = row >> 11, s = row & 2047;
                    const int part = n >> 10;
                    const int d1 = n & 1023;
                    const int h = d1 >> 6, hd = d1 & 63;
                    float* p = &g_qkv[part][((size_t)(b * H_ + h) * S_ + s) * HD_ + hd];
                    *(float2*)p = make_float2(v0, v1);
                } else {
                    *(float2*)(out + (size_t)row * 1024 + n) = make_float2(v0, v1);
                }
            }
        }
    }
}

// ---------------------------------------------------------------------------
// Kernel 2: flash-style causal attention, fp32 (byte-identical to R1 passing).
// ---------------------------------------------------------------------------
#define PAD_ 68
__global__ __launch_bounds__(256) void flash_attn() {
    extern __shared__ float sm[];
    float* qs = sm;                 // [d][r]  (Q^T, pre-scaled)
    float* ks = qs + 64 * PAD_;     // [d][c]  (K^T)
    float* vs = ks + 64 * PAD_;     // [k][c]
    float* ps = vs + 64 * PAD_;     // [r][k]

    const int tid = threadIdx.x;
    const int tx = tid & 15, ty = tid >> 4;
    const int q0 = blockIdx.x * 64;
    const int h  = blockIdx.y;
    const int b  = blockIdx.z;
    const float scale = 0.125f;  // 1/sqrt(64)

    const float* Q = g_qkv[0] + (size_t)(b * H_ + h) * S_ * HD_;
    const float* K = g_qkv[1] + (size_t)(b * H_ + h) * S_ * HD_;
    const float* V = g_qkv[2] + (size_t)(b * H_ + h) * S_ * HD_;

    for (int idx = tid; idx < 64 * 64; idx += 256) {
        const int r = idx >> 6, d = idx & 63;
        qs[d * PAD_ + r] = Q[(size_t)(q0 + r) * 64 + d] * scale;
    }

    const int r0 = ty * 4, c0 = tx * 4;
    float m_i[4], l_i[4], o[4][4];
#pragma unroll
    for (int i = 0; i < 4; i++) {
        m_i[i] = -1e30f;
        l_i[i] = 0.f;
#pragma unroll
        for (int j = 0; j < 4; j++) o[i][j] = 0.f;
    }
    __syncthreads();

    for (int j0 = 0; j0 <= q0; j0 += 64) {
        for (int idx = tid; idx < 64 * 64; idx += 256) {
            const int r = idx >> 6, d = idx & 63;
            ks[d * PAD_ + r] = K[(size_t)(j0 + r) * 64 + d];
        }
        for (int idx = tid; idx < 64 * 64; idx += 256) {
            const int k = idx >> 6, c = idx & 63;
            vs[k * PAD_ + c] = V[(size_t)(j0 + k) * 64 + c];
        }
        __syncthreads();

        float s[4][4];
#pragma unroll
        for (int i = 0; i < 4; i++)
#pragma unroll
            for (int j = 0; j < 4; j++) s[i][j] = 0.f;
        for (int d = 0; d < 64; d++) {
            const float4 aq = *(const float4*)&qs[d * PAD_ + r0];
            const float4 bk = *(const float4*)&ks[d * PAD_ + c0];
            const float a[4] = {aq.x, aq.y, aq.z, aq.w};
            const float bb2[4] = {bk.x, bk.y, bk.z, bk.w};
#pragma unroll
            for (int i = 0; i < 4; i++)
#pragma unroll
                for (int j = 0; j < 4; j++) s[i][j] += a[i] * bb2[j];
        }

        if (j0 == q0) {
#pragma unroll
            for (int i = 0; i < 4; i++)
#pragma unroll
                for (int j = 0; j < 4; j++)
                    if (c0 + j > r0 + i) s[i][j] = -1e30f;
        }

#pragma unroll
        for (int i = 0; i < 4; i++) {
            float t = fmaxf(fmaxf(s[i][0], s[i][1]), fmaxf(s[i][2], s[i][3]));
#pragma unroll
            for (int off = 8; off; off >>= 1)
                t = fmaxf(t, __shfl_xor_sync(0xffffffffu, t, off));
            const float mn = fmaxf(m_i[i], t);
            const float fi = __expf(m_i[i] - mn);
            float sum = 0.f;
#pragma unroll
            for (int j = 0; j < 4; j++) {
                s[i][j] = __expf(s[i][j] - mn);
                sum += s[i][j];
            }
#pragma unroll
            for (int off = 8; off; off >>= 1)
                sum += __shfl_xor_sync(0xffffffffu, sum, off);
            l_i[i] = l_i[i] * fi + sum;
            m_i[i] = mn;
#pragma unroll
            for (int j = 0; j < 4; j++) o[i][j] *= fi;
        }

#pragma unroll
        for (int i = 0; i < 4; i++)
#pragma unroll
            for (int j = 0; j < 4; j++) ps[(r0 + i) * PAD_ + c0 + j] = s[i][j];
        __syncthreads();

        for (int k = 0; k < 64; k++) {
            const float4 vv = *(const float4*)&vs[k * PAD_ + c0];
            const float vc[4] = {vv.x, vv.y, vv.z, vv.w};
            float pv[4];
#pragma unroll
            for (int i = 0; i < 4; i++) pv[i] = ps[(r0 + i) * PAD_ + k];
#pragma unroll
            for (int i = 0; i < 4; i++)
#pragma unroll
                for (int j = 0; j < 4; j++) o[i][j] += pv[i] * vc[j];
        }
        __syncthreads();
    }

#pragma unroll
    for (int i = 0; i < 4; i++) {
        const float inv = 1.f / l_i[i];
#pragma unroll
        for (int j = 0; j < 4; j++)
            g_ctx[(size_t)(b * S_ + q0 + r0 + i) * D_ + h * 64 + c0 + j] =
                o[i][j] * inv;
    }
}

// ---------------------------------------------------------------------------
extern "C" void kernel_launch(void* const* d_in, const int* in_sizes, int n_in,
                              void* d_out, int out_size) {
    const float* x      = (const float*)d_in[0];
    const float* W_attn = (const float*)d_in[1];
    const float* b_attn = (const float*)d_in[2];
    const float* W_proj = (const float*)d_in[3];
    const float* b_proj = (const float*)d_in[4];
    float* out = (float*)d_out;

    const int flash_smem = 4 * 64 * PAD_ * (int)sizeof(float);  // 69632 B
    cudaFuncSetAttribute(flash_attn, cudaFuncAttributeMaxDynamicSharedMemorySize,
                         flash_smem);

    // MODE 0: X = x (arg), scatter to g_qkv.   MODE 1: X = g_ctx (symbol).
    tc_gemm<3072, 0><<<dim3(3072 / 64, 8192 / 128), 256>>>(x, W_attn, b_attn, nullptr);
    flash_attn<<<dim3(S_ / 64, H_, B_), 256, flash_smem>>>();
    tc_gemm<1024, 1><<<dim3(1024 / 64, 8192 / 128), 256>>>(nullptr, W_proj, b_proj, out);
}

// round 8
// speedup vs baseline: 2.2656x; 1.5007x over previous
#include <cuda_runtime.h>
#include <cuda_bf16.h>
#include <math.h>
#include <stdint.h>

#define B_  4
#define S_  2048
#define D_  1024
#define H_  16
#define HD_ 64

// Scratch (allocation-free rule). Referenced ONLY from device code.
// g_qkv[0]: Q [b,h][s][hd] fp32   g_qkv[1]: K [b,h][s][hd] fp32
// g_qkv[2]: V TRANSPOSED [b,h][hd][s] fp32
__device__ float g_qkv[3][(size_t)B_ * H_ * S_ * HD_];
__device__ float g_ctx[(size_t)B_ * S_ * D_];

// ---------------------------------------------------------------------------
// helpers
// ---------------------------------------------------------------------------
__device__ __forceinline__ uint32_t prmt_hi(uint32_t a, uint32_t b) {
    // d = { lo16 = a[31:16] (even idx), hi16 = b[31:16] (odd idx) }
    uint32_t d;
    asm("prmt.b32 %0, %1, %2, 0x7632;" : "=r"(d) : "r"(a), "r"(b));
    return d;
}
__device__ __forceinline__ uint32_t cvt_bf16x2(float hi_val, float lo_val) {
    uint32_t d;
    asm("cvt.rn.bf16x2.f32 %0, %1, %2;" : "=r"(d) : "f"(hi_val), "f"(lo_val));
    return d;
}
__device__ __forceinline__ float ex2_(float x) {
    float y;
    asm("ex2.approx.ftz.f32 %0, %1;" : "=f"(y) : "f"(x));
    return y;
}
__device__ __forceinline__ void mma_bf16(float& c0, float& c1, float& c2, float& c3,
                                         uint32_t a0, uint32_t a1, uint32_t a2, uint32_t a3,
                                         uint32_t b0, uint32_t b1) {
    asm volatile(
        "mma.sync.aligned.m16n8k16.row.col.f32.bf16.bf16.f32 "
        "{%0,%1,%2,%3},{%4,%5,%6,%7},{%8,%9},{%0,%1,%2,%3};"
        : "+f"(c0), "+f"(c1), "+f"(c2), "+f"(c3)
        : "r"(a0), "r"(a1), "r"(a2), "r"(a3), "r"(b0), "r"(b1));
}

// ---------------------------------------------------------------------------
// Kernel 1/3: tensor-core GEMM (R5-passing structure; V stored transposed).
// ---------------------------------------------------------------------------
#define SROW 12

template <int LDN, int MODE>
__global__ __launch_bounds__(256) void tc_gemm(const float* __restrict__ Xarg,
                                               const float* __restrict__ W,
                                               const float* __restrict__ bias,
                                               float* __restrict__ out) {
    __shared__ uint32_t Ah[128 * SROW];
    __shared__ uint32_t Al[128 * SROW];
    __shared__ uint32_t Bh[64 * SROW];
    __shared__ uint32_t Bl[64 * SROW];

    const float* __restrict__ X = (MODE == 0) ? Xarg : (const float*)g_ctx;

    const int tid = threadIdx.x;
    const int lane = tid & 31;
    const int wid = tid >> 5;
    const int wm = wid >> 1;
    const int wn = wid & 1;
    const int grp = lane >> 2;
    const int tig = lane & 3;
    const int m0 = blockIdx.y * 128;
    const int n0 = blockIdx.x * 64;

    float acc[2][4][4];
#pragma unroll
    for (int mi = 0; mi < 2; mi++)
#pragma unroll
        for (int ni = 0; ni < 4; ni++)
#pragma unroll
            for (int r = 0; r < 4; r++) acc[mi][ni][r] = 0.f;

    const int am0 = tid >> 2;
    const int ak2 = (tid & 3) * 2;
    const int bk2 = tid & 7;
    const int bn4 = (tid >> 3) * 4;

    const int a_base = (wm * 32 + grp) * SROW + tig;
    const int b_base = (wn * 32 + grp) * SROW + tig;

#pragma unroll 1
    for (int kt = 0; kt < 1024; kt += 16) {
#pragma unroll
        for (int i = 0; i < 2; i++) {
            const int m = am0 + i * 64;
            const float4 v = *(const float4*)(X + (size_t)(m0 + m) * 1024 + kt + ak2 * 2);
            const uint32_t bx = __float_as_uint(v.x), by = __float_as_uint(v.y);
            const uint32_t bz = __float_as_uint(v.z), bw = __float_as_uint(v.w);
            Ah[m * SROW + ak2]     = prmt_hi(bx, by);
            Ah[m * SROW + ak2 + 1] = prmt_hi(bz, bw);
            const float lx = v.x - __uint_as_float(bx & 0xffff0000u);
            const float ly = v.y - __uint_as_float(by & 0xffff0000u);
            const float lz = v.z - __uint_as_float(bz & 0xffff0000u);
            const float lw = v.w - __uint_as_float(bw & 0xffff0000u);
            Al[m * SROW + ak2]     = cvt_bf16x2(ly, lx);
            Al[m * SROW + ak2 + 1] = cvt_bf16x2(lw, lz);
        }
        if (tid < 128) {
            const float4 v0 = *(const float4*)(W + (size_t)(kt + 2 * bk2) * LDN + n0 + bn4);
            const float4 v1 = *(const float4*)(W + (size_t)(kt + 2 * bk2 + 1) * LDN + n0 + bn4);
            uint32_t be, bo;
            be = __float_as_uint(v0.x); bo = __float_as_uint(v1.x);
            Bh[(bn4 + 0) * SROW + bk2] = prmt_hi(be, bo);
            Bl[(bn4 + 0) * SROW + bk2] =
                cvt_bf16x2(v1.x - __uint_as_float(bo & 0xffff0000u),
                           v0.x - __uint_as_float(be & 0xffff0000u));
            be = __float_as_uint(v0.y); bo = __float_as_uint(v1.y);
            Bh[(bn4 + 1) * SROW + bk2] = prmt_hi(be, bo);
            Bl[(bn4 + 1) * SROW + bk2] =
                cvt_bf16x2(v1.y - __uint_as_float(bo & 0xffff0000u),
                           v0.y - __uint_as_float(be & 0xffff0000u));
            be = __float_as_uint(v0.z); bo = __float_as_uint(v1.z);
            Bh[(bn4 + 2) * SROW + bk2] = prmt_hi(be, bo);
            Bl[(bn4 + 2) * SROW + bk2] =
                cvt_bf16x2(v1.z - __uint_as_float(bo & 0xffff0000u),
                           v0.z - __uint_as_float(be & 0xffff0000u));
            be = __float_as_uint(v0.w); bo = __float_as_uint(v1.w);
            Bh[(bn4 + 3) * SROW + bk2] = prmt_hi(be, bo);
            Bl[(bn4 + 3) * SROW + bk2] =
                cvt_bf16x2(v1.w - __uint_as_float(bo & 0xffff0000u),
                           v0.w - __uint_as_float(be & 0xffff0000u));
        }
        __syncthreads();

        const uint32_t bh00 = Bh[b_base + 0 * 8 * SROW], bh01 = Bh[b_base + 0 * 8 * SROW + 4];
        const uint32_t bl00 = Bl[b_base + 0 * 8 * SROW], bl01 = Bl[b_base + 0 * 8 * SROW + 4];
        const uint32_t bh10 = Bh[b_base + 1 * 8 * SROW], bh11 = Bh[b_base + 1 * 8 * SROW + 4];
        const uint32_t bl10 = Bl[b_base + 1 * 8 * SROW], bl11 = Bl[b_base + 1 * 8 * SROW + 4];
        const uint32_t bh20 = Bh[b_base + 2 * 8 * SROW], bh21 = Bh[b_base + 2 * 8 * SROW + 4];
        const uint32_t bl20 = Bl[b_base + 2 * 8 * SROW], bl21 = Bl[b_base + 2 * 8 * SROW + 4];
        const uint32_t bh30 = Bh[b_base + 3 * 8 * SROW], bh31 = Bh[b_base + 3 * 8 * SROW + 4];
        const uint32_t bl30 = Bl[b_base + 3 * 8 * SROW], bl31 = Bl[b_base + 3 * 8 * SROW + 4];

#pragma unroll
        for (int mi = 0; mi < 2; mi++) {
            const int ab = a_base + mi * 16 * SROW;
            const uint32_t ah0 = Ah[ab];
            const uint32_t ah1 = Ah[ab + 8 * SROW];
            const uint32_t ah2 = Ah[ab + 4];
            const uint32_t ah3 = Ah[ab + 8 * SROW + 4];
            const uint32_t al0 = Al[ab];
            const uint32_t al1 = Al[ab + 8 * SROW];
            const uint32_t al2 = Al[ab + 4];
            const uint32_t al3 = Al[ab + 8 * SROW + 4];

            mma_bf16(acc[mi][0][0], acc[mi][0][1], acc[mi][0][2], acc[mi][0][3],
                     ah0, ah1, ah2, ah3, bh00, bh01);
            mma_bf16(acc[mi][0][0], acc[mi][0][1], acc[mi][0][2], acc[mi][0][3],
                     ah0, ah1, ah2, ah3, bl00, bl01);
            mma_bf16(acc[mi][0][0], acc[mi][0][1], acc[mi][0][2], acc[mi][0][3],
                     al0, al1, al2, al3, bh00, bh01);

            mma_bf16(acc[mi][1][0], acc[mi][1][1], acc[mi][1][2], acc[mi][1][3],
                     ah0, ah1, ah2, ah3, bh10, bh11);
            mma_bf16(acc[mi][1][0], acc[mi][1][1], acc[mi][1][2], acc[mi][1][3],
                     ah0, ah1, ah2, ah3, bl10, bl11);
            mma_bf16(acc[mi][1][0], acc[mi][1][1], acc[mi][1][2], acc[mi][1][3],
                     al0, al1, al2, al3, bh10, bh11);

            mma_bf16(acc[mi][2][0], acc[mi][2][1], acc[mi][2][2], acc[mi][2][3],
                     ah0, ah1, ah2, ah3, bh20, bh21);
            mma_bf16(acc[mi][2][0], acc[mi][2][1], acc[mi][2][2], acc[mi][2][3],
                     ah0, ah1, ah2, ah3, bl20, bl21);
            mma_bf16(acc[mi][2][0], acc[mi][2][1], acc[mi][2][2], acc[mi][2][3],
                     al0, al1, al2, al3, bh20, bh21);

            mma_bf16(acc[mi][3][0], acc[mi][3][1], acc[mi][3][2], acc[mi][3][3],
                     ah0, ah1, ah2, ah3, bh30, bh31);
            mma_bf16(acc[mi][3][0], acc[mi][3][1], acc[mi][3][2], acc[mi][3][3],
                     ah0, ah1, ah2, ah3, bl30, bl31);
            mma_bf16(acc[mi][3][0], acc[mi][3][1], acc[mi][3][2], acc[mi][3][3],
                     al0, al1, al2, al3, bh30, bh31);
        }
        __syncthreads();
    }

#pragma unroll
    for (int mi = 0; mi < 2; mi++) {
#pragma unroll
        for (int rr = 0; rr < 2; rr++) {
            const int row = m0 + wm * 32 + mi * 16 + grp + rr * 8;
#pragma unroll
            for (int ni = 0; ni < 4; ni++) {
                const int n = n0 + wn * 32 + ni * 8 + tig * 2;
                const float v0 = acc[mi][ni][rr * 2 + 0] + bias[n];
                const float v1 = acc[mi][ni][rr * 2 + 1] + bias[n + 1];
                if (MODE == 0) {
                    const int b = row >> 11, s = row & 2047;
                    const int part = n >> 10;
                    const int d1 = n & 1023;
                    const int h = d1 >> 6, hd = d1 & 63;
                    if (part == 2) {
                        // V transposed: [b,h][hd][s]
                        float* p = &g_qkv[2][((size_t)(b * H_ + h) * HD_ + hd) * S_ + s];
                        p[0] = v0;
                        p[S_] = v1;
                    } else {
                        float* p = &g_qkv[part][((size_t)(b * H_ + h) * S_ + s) * HD_ + hd];
                        *(float2*)p = make_float2(v0, v1);
                    }
                } else {
                    *(float2*)(out + (size_t)row * 1024 + n) = make_float2(v0, v1);
                }
            }
        }
    }
}

// ---------------------------------------------------------------------------
// Kernel 2: tensor-core flash attention (bf16 2-term split, fp32 softmax).
// Block = 128 q-rows, 8 warps x 16 rows. Key tiles of 64.
// FIX vs R6: ntiles = 2*qt + 2 (was qt+2 -> dropped half the key tiles).
// ---------------------------------------------------------------------------
#define STR 36  // smem row stride in words (32 k2 slots + 4 pad)

__global__ __launch_bounds__(256) void flash_tc() {
    extern __shared__ uint32_t sm4[];
    uint32_t* qh = sm4;                // [128][STR]
    uint32_t* ql = qh + 128 * STR;
    uint32_t* kh = ql + 128 * STR;     // [64][STR]  rows = key
    uint32_t* kl = kh + 64 * STR;
    uint32_t* vh = kl + 64 * STR;      // [64][STR]  rows = hd, k = key pairs
    uint32_t* vl = vh + 64 * STR;

    const int tid = threadIdx.x;
    const int lane = tid & 31;
    const int wid = tid >> 5;
    const int grp = lane >> 2;
    const int tig = lane & 3;
    const int qt = gridDim.x - 1 - blockIdx.x;   // long blocks first
    const int q0 = qt * 128;
    const int h = blockIdx.y, b = blockIdx.z;

    const float* Qg  = g_qkv[0] + (size_t)(b * H_ + h) * S_ * HD_;
    const float* Kg  = g_qkv[1] + (size_t)(b * H_ + h) * S_ * HD_;
    const float* Vtg = g_qkv[2] + (size_t)(b * H_ + h) * HD_ * S_;

    // ---- load Q once: scale by 0.125*log2(e), split hi/lo ----
    {
        const float cs = 0.125f * 1.4426950408889634f;
        const int r = tid >> 1, hb = (tid & 1) * 32;
        const float* src = Qg + (size_t)(q0 + r) * 64 + hb;
        uint32_t* dh = qh + r * STR + (hb >> 1);
        uint32_t* dl = ql + r * STR + (hb >> 1);
#pragma unroll
        for (int i = 0; i < 8; i++) {
            float4 v = *(const float4*)(src + 4 * i);
            v.x *= cs; v.y *= cs; v.z *= cs; v.w *= cs;
            const uint32_t bx = __float_as_uint(v.x), by = __float_as_uint(v.y);
            const uint32_t bz = __float_as_uint(v.z), bw = __float_as_uint(v.w);
            dh[2 * i]     = prmt_hi(bx, by);
            dh[2 * i + 1] = prmt_hi(bz, bw);
            dl[2 * i]     = cvt_bf16x2(v.y - __uint_as_float(by & 0xffff0000u),
                                       v.x - __uint_as_float(bx & 0xffff0000u));
            dl[2 * i + 1] = cvt_bf16x2(v.w - __uint_as_float(bw & 0xffff0000u),
                                       v.z - __uint_as_float(bz & 0xffff0000u));
        }
    }

    float m0r = -1e30f, m1r = -1e30f, l0 = 0.f, l1 = 0.f;
    float oacc[8][4];
#pragma unroll
    for (int n = 0; n < 8; n++)
#pragma unroll
        for (int r = 0; r < 4; r++) oacc[n][r] = 0.f;

    __syncthreads();

    const int row_max_w = q0 + wid * 16 + 15;  // highest q row of this warp
    const int ntiles = 2 * qt + 2;             // keys 0 .. q0+127

#pragma unroll 1
    for (int t = 0; t < ntiles; t++) {
        const int j0 = t * 64;

        // ---- load K tile (rows = key, over hd) ----
        {
            const int r = tid >> 2, hb2 = (tid & 3) * 16;
            const float* src = Kg + (size_t)(j0 + r) * 64 + hb2;
            uint32_t* dh = kh + r * STR + (hb2 >> 1);
            uint32_t* dl = kl + r * STR + (hb2 >> 1);
#pragma unroll
            for (int i = 0; i < 4; i++) {
                const float4 v = *(const float4*)(src + 4 * i);
                const uint32_t bx = __float_as_uint(v.x), by = __float_as_uint(v.y);
                const uint32_t bz = __float_as_uint(v.z), bw = __float_as_uint(v.w);
                dh[2 * i]     = prmt_hi(bx, by);
                dh[2 * i + 1] = prmt_hi(bz, bw);
                dl[2 * i]     = cvt_bf16x2(v.y - __uint_as_float(by & 0xffff0000u),
                                           v.x - __uint_as_float(bx & 0xffff0000u));
                dl[2 * i + 1] = cvt_bf16x2(v.w - __uint_as_float(bw & 0xffff0000u),
                                           v.z - __uint_as_float(bz & 0xffff0000u));
            }
        }
        // ---- load V tile transposed (rows = hd, over key pairs) ----
        {
            const int d = tid >> 2, kb = (tid & 3) * 16;
            const float* src = Vtg + (size_t)d * S_ + j0 + kb;
            uint32_t* dh = vh + d * STR + (kb >> 1);
            uint32_t* dl = vl + d * STR + (kb >> 1);
#pragma unroll
            for (int i = 0; i < 4; i++) {
                const float4 v = *(const float4*)(src + 4 * i);
                const uint32_t bx = __float_as_uint(v.x), by = __float_as_uint(v.y);
                const uint32_t bz = __float_as_uint(v.z), bw = __float_as_uint(v.w);
                dh[2 * i]     = prmt_hi(bx, by);
                dh[2 * i + 1] = prmt_hi(bz, bw);
                dl[2 * i]     = cvt_bf16x2(v.y - __uint_as_float(by & 0xffff0000u),
                                           v.x - __uint_as_float(bx & 0xffff0000u));
                dl[2 * i + 1] = cvt_bf16x2(v.w - __uint_as_float(bw & 0xffff0000u),
                                           v.z - __uint_as_float(bz & 0xffff0000u));
            }
        }
        __syncthreads();

        if (row_max_w >= j0) {   // warp has at least one unmasked row
            // ---- S = Q @ K^T (scaled, log2 domain) ----
            float sacc[8][4];
#pragma unroll
            for (int n = 0; n < 8; n++)
#pragma unroll
                for (int r = 0; r < 4; r++) sacc[n][r] = 0.f;

#pragma unroll
            for (int jj = 0; jj < 4; jj++) {
                const int ab = (wid * 16 + grp) * STR + 8 * jj + tig;
                const uint32_t ah0 = qh[ab];
                const uint32_t ah1 = qh[ab + 8 * STR];
                const uint32_t ah2 = qh[ab + 4];
                const uint32_t ah3 = qh[ab + 8 * STR + 4];
                const uint32_t al0 = ql[ab];
                const uint32_t al1 = ql[ab + 8 * STR];
                const uint32_t al2 = ql[ab + 4];
                const uint32_t al3 = ql[ab + 8 * STR + 4];
#pragma unroll
                for (int n = 0; n < 8; n++) {
                    const int kb = (8 * n + grp) * STR + 8 * jj + tig;
                    const uint32_t bh0 = kh[kb], bh1 = kh[kb + 4];
                    const uint32_t bl0 = kl[kb], bl1 = kl[kb + 4];
                    mma_bf16(sacc[n][0], sacc[n][1], sacc[n][2], sacc[n][3],
                             ah0, ah1, ah2, ah3, bh0, bh1);
                    mma_bf16(sacc[n][0], sacc[n][1], sacc[n][2], sacc[n][3],
                             ah0, ah1, ah2, ah3, bl0, bl1);
                    mma_bf16(sacc[n][0], sacc[n][1], sacc[n][2], sacc[n][3],
                             al0, al1, al2, al3, bh0, bh1);
                }
            }

            // ---- causal mask (only near diagonal) ----
            const int row0 = q0 + wid * 16 + grp;
            const int row1 = row0 + 8;
            if (j0 + 63 > q0) {
#pragma unroll
                for (int n = 0; n < 8; n++) {
                    const int c = j0 + 8 * n + tig * 2;
                    if (c > row0)     sacc[n][0] = -1e30f;
                    if (c + 1 > row0) sacc[n][1] = -1e30f;
                    if (c > row1)     sacc[n][2] = -1e30f;
                    if (c + 1 > row1) sacc[n][3] = -1e30f;
                }
            }

            // ---- online softmax (log2 domain), quad reductions ----
            float mx0 = -1e30f, mx1 = -1e30f;
#pragma unroll
            for (int n = 0; n < 8; n++) {
                mx0 = fmaxf(mx0, fmaxf(sacc[n][0], sacc[n][1]));
                mx1 = fmaxf(mx1, fmaxf(sacc[n][2], sacc[n][3]));
            }
            mx0 = fmaxf(mx0, __shfl_xor_sync(0xffffffffu, mx0, 1));
            mx0 = fmaxf(mx0, __shfl_xor_sync(0xffffffffu, mx0, 2));
            mx1 = fmaxf(mx1, __shfl_xor_sync(0xffffffffu, mx1, 1));
            mx1 = fmaxf(mx1, __shfl_xor_sync(0xffffffffu, mx1, 2));

            const float mn0 = fmaxf(m0r, mx0);
            const float mn1 = fmaxf(m1r, mx1);
            const float fi0 = ex2_(m0r - mn0);
            const float fi1 = ex2_(m1r - mn1);
            m0r = mn0; m1r = mn1;

            float sum0 = 0.f, sum1 = 0.f;
#pragma unroll
            for (int n = 0; n < 8; n++) {
                sacc[n][0] = ex2_(sacc[n][0] - mn0);
                sacc[n][1] = ex2_(sacc[n][1] - mn0);
                sacc[n][2] = ex2_(sacc[n][2] - mn1);
                sacc[n][3] = ex2_(sacc[n][3] - mn1);
                sum0 += sacc[n][0] + sacc[n][1];
                sum1 += sacc[n][2] + sacc[n][3];
            }
            sum0 += __shfl_xor_sync(0xffffffffu, sum0, 1);
            sum0 += __shfl_xor_sync(0xffffffffu, sum0, 2);
            sum1 += __shfl_xor_sync(0xffffffffu, sum1, 1);
            sum1 += __shfl_xor_sync(0xffffffffu, sum1, 2);
            l0 = l0 * fi0 + sum0;
            l1 = l1 * fi1 + sum1;

#pragma unroll
            for (int n = 0; n < 8; n++) {
                oacc[n][0] *= fi0; oacc[n][1] *= fi0;
                oacc[n][2] *= fi1; oacc[n][3] *= fi1;
            }

            // ---- O += P @ V  (P split hi/lo from sacc; C-frag == A-frag) ----
#pragma unroll
            for (int jj = 0; jj < 4; jj++) {
                const uint32_t p00 = __float_as_uint(sacc[2 * jj][0]);
                const uint32_t p01 = __float_as_uint(sacc[2 * jj][1]);
                const uint32_t p02 = __float_as_uint(sacc[2 * jj][2]);
                const uint32_t p03 = __float_as_uint(sacc[2 * jj][3]);
                const uint32_t p10 = __float_as_uint(sacc[2 * jj + 1][0]);
                const uint32_t p11 = __float_as_uint(sacc[2 * jj + 1][1]);
                const uint32_t p12 = __float_as_uint(sacc[2 * jj + 1][2]);
                const uint32_t p13 = __float_as_uint(sacc[2 * jj + 1][3]);

                const uint32_t ph0 = prmt_hi(p00, p01);
                const uint32_t ph1 = prmt_hi(p02, p03);
                const uint32_t ph2 = prmt_hi(p10, p11);
                const uint32_t ph3 = prmt_hi(p12, p13);
                const uint32_t pl0 = cvt_bf16x2(
                    sacc[2 * jj][1] - __uint_as_float(p01 & 0xffff0000u),
                    sacc[2 * jj][0] - __uint_as_float(p00 & 0xffff0000u));
                const uint32_t pl1 = cvt_bf16x2(
                    sacc[2 * jj][3] - __uint_as_float(p03 & 0xffff0000u),
                    sacc[2 * jj][2] - __uint_as_float(p02 & 0xffff0000u));
                const uint32_t pl2 = cvt_bf16x2(
                    sacc[2 * jj + 1][1] - __uint_as_float(p11 & 0xffff0000u),
                    sacc[2 * jj + 1][0] - __uint_as_float(p10 & 0xffff0000u));
                const uint32_t pl3 = cvt_bf16x2(
                    sacc[2 * jj + 1][3] - __uint_as_float(p13 & 0xffff0000u),
                    sacc[2 * jj + 1][2] - __uint_as_float(p12 & 0xffff0000u));

#pragma unroll
                for (int n = 0; n < 8; n++) {
                    const int vb = (8 * n + grp) * STR + 8 * jj + tig;
                    const uint32_t bh0 = vh[vb], bh1 = vh[vb + 4];
                    const uint32_t bl0 = vl[vb], bl1 = vl[vb + 4];
                    mma_bf16(oacc[n][0], oacc[n][1], oacc[n][2], oacc[n][3],
                             ph0, ph1, ph2, ph3, bh0, bh1);
                    mma_bf16(oacc[n][0], oacc[n][1], oacc[n][2], oacc[n][3],
                             ph0, ph1, ph2, ph3, bl0, bl1);
                    mma_bf16(oacc[n][0], oacc[n][1], oacc[n][2], oacc[n][3],
                             pl0, pl1, pl2, pl3, bh0, bh1);
                }
            }
        }
        __syncthreads();
    }

    // ---- epilogue: normalize, write g_ctx [b*S+row][h*64+col] ----
    const float inv0 = 1.f / l0;
    const float inv1 = 1.f / l1;
    const int row0 = q0 + wid * 16 + grp;
#pragma unroll
    for (int n = 0; n < 8; n++) {
        const int col = h * 64 + 8 * n + tig * 2;
        *(float2*)&g_ctx[(size_t)(b * S_ + row0) * D_ + col] =
            make_float2(oacc[n][0] * inv0, oacc[n][1] * inv0);
        *(float2*)&g_ctx[(size_t)(b * S_ + row0 + 8) * D_ + col] =
            make_float2(oacc[n][2] * inv1, oacc[n][3] * inv1);
    }
}

// ---------------------------------------------------------------------------
extern "C" void kernel_launch(void* const* d_in, const int* in_sizes, int n_in,
                              void* d_out, int out_size) {
    const float* x      = (const float*)d_in[0];
    const float* W_attn = (const float*)d_in[1];
    const float* b_attn = (const float*)d_in[2];
    const float* W_proj = (const float*)d_in[3];
    const float* b_proj = (const float*)d_in[4];
    float* out = (float*)d_out;

    const int flash_smem = (128 * STR * 2 + 64 * STR * 4) * (int)sizeof(uint32_t); // 73728
    cudaFuncSetAttribute(flash_tc, cudaFuncAttributeMaxDynamicSharedMemorySize,
                         flash_smem);

    tc_gemm<3072, 0><<<dim3(3072 / 64, 8192 / 128), 256>>>(x, W_attn, b_attn, nullptr);
    flash_tc<<<dim3(S_ / 128, H_, B_), 256, flash_smem>>>();
    tc_gemm<1024, 1><<<dim3(1024 / 64, 8192 / 128), 256>>>(nullptr, W_proj, b_proj, out);
}

// round 9
// speedup vs baseline: 2.4562x; 1.0841x over previous
#include <cuda_runtime.h>
#include <cuda_bf16.h>
#include <math.h>
#include <stdint.h>

#define B_  4
#define S_  2048
#define D_  1024
#define H_  16
#define HD_ 64

// Scratch (allocation-free rule). Referenced ONLY from device code.
// g_qkv[0]: Q [b,h][s][hd]  g_qkv[1]: K [b,h][s][hd]  g_qkv[2]: V^T [b,h][hd][s]
__device__ float g_qkv[3][(size_t)B_ * H_ * S_ * HD_];
__device__ float g_ctx[(size_t)B_ * S_ * D_];

// ---------------------------------------------------------------------------
// helpers
// ---------------------------------------------------------------------------
__device__ __forceinline__ uint32_t prmt_hi(uint32_t a, uint32_t b) {
    uint32_t d;
    asm("prmt.b32 %0, %1, %2, 0x7632;" : "=r"(d) : "r"(a), "r"(b));
    return d;
}
__device__ __forceinline__ uint32_t cvt_bf16x2(float hi_val, float lo_val) {
    uint32_t d;
    asm("cvt.rn.bf16x2.f32 %0, %1, %2;" : "=r"(d) : "f"(hi_val), "f"(lo_val));
    return d;
}
__device__ __forceinline__ float ex2_(float x) {
    float y;
    asm("ex2.approx.ftz.f32 %0, %1;" : "=f"(y) : "f"(x));
    return y;
}
__device__ __forceinline__ void mma_bf16(float& c0, float& c1, float& c2, float& c3,
                                         uint32_t a0, uint32_t a1, uint32_t a2, uint32_t a3,
                                         uint32_t b0, uint32_t b1) {
    asm volatile(
        "mma.sync.aligned.m16n8k16.row.col.f32.bf16.bf16.f32 "
        "{%0,%1,%2,%3},{%4,%5,%6,%7},{%8,%9},{%0,%1,%2,%3};"
        : "+f"(c0), "+f"(c1), "+f"(c2), "+f"(c3)
        : "r"(a0), "r"(a1), "r"(a2), "r"(a3), "r"(b0), "r"(b1));
}
// A-row staging: consecutive-k float4 -> hi pair + lo pair
__device__ __forceinline__ void split_store_row(uint32_t* Hh, uint32_t* Hl, int idx, float4 v) {
    const uint32_t bx = __float_as_uint(v.x), by = __float_as_uint(v.y);
    const uint32_t bz = __float_as_uint(v.z), bw = __float_as_uint(v.w);
    Hh[idx]     = prmt_hi(bx, by);
    Hh[idx + 1] = prmt_hi(bz, bw);
    Hl[idx]     = cvt_bf16x2(v.y - __uint_as_float(by & 0xffff0000u),
                             v.x - __uint_as_float(bx & 0xffff0000u));
    Hl[idx + 1] = cvt_bf16x2(v.w - __uint_as_float(bw & 0xffff0000u),
                             v.z - __uint_as_float(bz & 0xffff0000u));
}

// ---------------------------------------------------------------------------
// Kernel 1/3: tensor-core GEMM v2.
// Block tile 256x128 (grid y=M/256, x=N/128), 256 threads = 8 warps (4M x 2N),
// warp tile 64x64 = 4mi x 8ni m16n8k16, split-3 bf16.
// Register LDG prefetch of next k-tile hides global latency (1 block/SM).
// L1 bytes/MMA: 146 vs 292 in the R8 version.
// ---------------------------------------------------------------------------
#define SROW 12

template <int LDN, int MODE>
__global__ __launch_bounds__(256) void tc_gemm(const float* __restrict__ Xarg,
                                               const float* __restrict__ W,
                                               const float* __restrict__ bias,
                                               float* __restrict__ out) {
    __shared__ uint32_t Ah[256 * SROW];   // 12KB
    __shared__ uint32_t Al[256 * SROW];
    __shared__ uint32_t Bh[128 * SROW];   // 6KB
    __shared__ uint32_t Bl[128 * SROW];   // total 36KB

    const float* __restrict__ X = (MODE == 0) ? Xarg : (const float*)g_ctx;

    const int tid = threadIdx.x;
    const int lane = tid & 31;
    const int wid = tid >> 5;
    const int wm = wid >> 1;      // 0..3 : 64-row band
    const int wn = wid & 1;       // 0..1 : 64-col band
    const int grp = lane >> 2;    // 0..7
    const int tig = lane & 3;     // 0..3
    const int m0 = blockIdx.y * 256;
    const int n0 = blockIdx.x * 128;

    float acc[4][8][4];
#pragma unroll
    for (int mi = 0; mi < 4; mi++)
#pragma unroll
        for (int ni = 0; ni < 8; ni++)
#pragma unroll
            for (int r = 0; r < 4; r++) acc[mi][ni][r] = 0.f;

    // A loader: rows am0 + {0,64,128,192}, 1 float4 each (k2 base ak2)
    const int am0 = tid >> 2;             // 0..63
    const int ak2 = (tid & 3) * 2;        // 0,2,4,6
    // B loader: k rows 2*bk2, 2*bk2+1; 4 cols at bn4
    const int bk2 = tid & 7;              // 0..7
    const int bn4 = (tid >> 3) * 4;       // 0..124

    const int a_base = (wm * 64 + grp) * SROW + tig;
    const int b_base = (wn * 64 + grp) * SROW + tig;

    const float* Xp = X + (size_t)(m0 + am0) * 1024 + ak2 * 2;
    const float* Wp0 = W + (size_t)(2 * bk2) * LDN + n0 + bn4;
    const float* Wp1 = W + (size_t)(2 * bk2 + 1) * LDN + n0 + bn4;

    // ---- prefetch k-tile 0 into registers ----
    float4 a_pre0 = *(const float4*)(Xp);
    float4 a_pre1 = *(const float4*)(Xp + (size_t)64 * 1024);
    float4 a_pre2 = *(const float4*)(Xp + (size_t)128 * 1024);
    float4 a_pre3 = *(const float4*)(Xp + (size_t)192 * 1024);
    float4 b_pre0 = *(const float4*)(Wp0);
    float4 b_pre1 = *(const float4*)(Wp1);

#pragma unroll 1
    for (int kt = 0; kt < 1024; kt += 16) {
        // ---- convert + STS current tile from prefetch regs ----
        split_store_row(Ah, Al, (am0 + 0) * SROW + ak2, a_pre0);
        split_store_row(Ah, Al, (am0 + 64) * SROW + ak2, a_pre1);
        split_store_row(Ah, Al, (am0 + 128) * SROW + ak2, a_pre2);
        split_store_row(Ah, Al, (am0 + 192) * SROW + ak2, a_pre3);
        {
            // column-wise pairing: (v0.j even-k, v1.j odd-k)
            const float e0 = b_pre0.x, e1 = b_pre0.y, e2 = b_pre0.z, e3 = b_pre0.w;
            const float o0 = b_pre1.x, o1 = b_pre1.y, o2 = b_pre1.z, o3 = b_pre1.w;
            uint32_t be, bo;
            be = __float_as_uint(e0); bo = __float_as_uint(o0);
            Bh[(bn4 + 0) * SROW + bk2] = prmt_hi(be, bo);
            Bl[(bn4 + 0) * SROW + bk2] =
                cvt_bf16x2(o0 - __uint_as_float(bo & 0xffff0000u),
                           e0 - __uint_as_float(be & 0xffff0000u));
            be = __float_as_uint(e1); bo = __float_as_uint(o1);
            Bh[(bn4 + 1) * SROW + bk2] = prmt_hi(be, bo);
            Bl[(bn4 + 1) * SROW + bk2] =
                cvt_bf16x2(o1 - __uint_as_float(bo & 0xffff0000u),
                           e1 - __uint_as_float(be & 0xffff0000u));
            be = __float_as_uint(e2); bo = __float_as_uint(o2);
            Bh[(bn4 + 2) * SROW + bk2] = prmt_hi(be, bo);
            Bl[(bn4 + 2) * SROW + bk2] =
                cvt_bf16x2(o2 - __uint_as_float(bo & 0xffff0000u),
                           e2 - __uint_as_float(be & 0xffff0000u));
            be = __float_as_uint(e3); bo = __float_as_uint(o3);
            Bh[(bn4 + 3) * SROW + bk2] = prmt_hi(be, bo);
            Bl[(bn4 + 3) * SROW + bk2] =
                cvt_bf16x2(o3 - __uint_as_float(bo & 0xffff0000u),
                           e3 - __uint_as_float(be & 0xffff0000u));
        }
        __syncthreads();

        // ---- issue prefetch for next k-tile (hides under MMA phase) ----
        if (kt + 16 < 1024) {
            const float* xp = Xp + kt + 16;
            a_pre0 = *(const float4*)(xp);
            a_pre1 = *(const float4*)(xp + (size_t)64 * 1024);
            a_pre2 = *(const float4*)(xp + (size_t)128 * 1024);
            a_pre3 = *(const float4*)(xp + (size_t)192 * 1024);
            b_pre0 = *(const float4*)(Wp0 + (size_t)(kt + 16) * LDN);
            b_pre1 = *(const float4*)(Wp1 + (size_t)(kt + 16) * LDN);
        }

        // ---- B fragments held (32 regs) ----
        uint32_t bh[8][2], bl[8][2];
#pragma unroll
        for (int ni = 0; ni < 8; ni++) {
            const int bb = b_base + ni * 8 * SROW;
            bh[ni][0] = Bh[bb]; bh[ni][1] = Bh[bb + 4];
            bl[ni][0] = Bl[bb]; bl[ni][1] = Bl[bb + 4];
        }

#pragma unroll
        for (int mi = 0; mi < 4; mi++) {
            const int ab = a_base + mi * 16 * SROW;
            const uint32_t ah0 = Ah[ab];
            const uint32_t ah1 = Ah[ab + 8 * SROW];
            const uint32_t ah2 = Ah[ab + 4];
            const uint32_t ah3 = Ah[ab + 8 * SROW + 4];
            const uint32_t al0 = Al[ab];
            const uint32_t al1 = Al[ab + 8 * SROW];
            const uint32_t al2 = Al[ab + 4];
            const uint32_t al3 = Al[ab + 8 * SROW + 4];
#pragma unroll
            for (int ni = 0; ni < 8; ni++) {
                mma_bf16(acc[mi][ni][0], acc[mi][ni][1], acc[mi][ni][2], acc[mi][ni][3],
                         ah0, ah1, ah2, ah3, bh[ni][0], bh[ni][1]);
                mma_bf16(acc[mi][ni][0], acc[mi][ni][1], acc[mi][ni][2], acc[mi][ni][3],
                         ah0, ah1, ah2, ah3, bl[ni][0], bl[ni][1]);
                mma_bf16(acc[mi][ni][0], acc[mi][ni][1], acc[mi][ni][2], acc[mi][ni][3],
                         al0, al1, al2, al3, bh[ni][0], bh[ni][1]);
            }
        }
        __syncthreads();
    }

    // ---- epilogue ----
#pragma unroll
    for (int mi = 0; mi < 4; mi++) {
#pragma unroll
        for (int rr = 0; rr < 2; rr++) {
            const int row = m0 + wm * 64 + mi * 16 + grp + rr * 8;
#pragma unroll
            for (int ni = 0; ni < 8; ni++) {
                const int n = n0 + wn * 64 + ni * 8 + tig * 2;
                const float v0 = acc[mi][ni][rr * 2 + 0] + bias[n];
                const float v1 = acc[mi][ni][rr * 2 + 1] + bias[n + 1];
                if (MODE == 0) {
                    const int b = row >> 11, s = row & 2047;
                    const int part = n >> 10;
                    const int d1 = n & 1023;
                    const int h = d1 >> 6, hd = d1 & 63;
                    if (part == 2) {
                        float* p = &g_qkv[2][((size_t)(b * H_ + h) * HD_ + hd) * S_ + s];
                        p[0] = v0;
                        p[S_] = v1;
                    } else {
                        float* p = &g_qkv[part][((size_t)(b * H_ + h) * S_ + s) * HD_ + hd];
                        *(float2*)p = make_float2(v0, v1);
                    }
                } else {
                    *(float2*)(out + (size_t)row * 1024 + n) = make_float2(v0, v1);
                }
            }
        }
    }
}

// ---------------------------------------------------------------------------
// Kernel 2: tensor-core flash attention (FROZEN from R8-passing).
// ---------------------------------------------------------------------------
#define STR 36

__global__ __launch_bounds__(256) void flash_tc() {
    extern __shared__ uint32_t sm4[];
    uint32_t* qh = sm4;
    uint32_t* ql = qh + 128 * STR;
    uint32_t* kh = ql + 128 * STR;
    uint32_t* kl = kh + 64 * STR;
    uint32_t* vh = kl + 64 * STR;
    uint32_t* vl = vh + 64 * STR;

    const int tid = threadIdx.x;
    const int lane = tid & 31;
    const int wid = tid >> 5;
    const int grp = lane >> 2;
    const int tig = lane & 3;
    const int qt = gridDim.x - 1 - blockIdx.x;
    const int q0 = qt * 128;
    const int h = blockIdx.y, b = blockIdx.z;

    const float* Qg  = g_qkv[0] + (size_t)(b * H_ + h) * S_ * HD_;
    const float* Kg  = g_qkv[1] + (size_t)(b * H_ + h) * S_ * HD_;
    const float* Vtg = g_qkv[2] + (size_t)(b * H_ + h) * HD_ * S_;

    {
        const float cs = 0.125f * 1.4426950408889634f;
        const int r = tid >> 1, hb = (tid & 1) * 32;
        const float* src = Qg + (size_t)(q0 + r) * 64 + hb;
        uint32_t* dh = qh + r * STR + (hb >> 1);
        uint32_t* dl = ql + r * STR + (hb >> 1);
#pragma unroll
        for (int i = 0; i < 8; i++) {
            float4 v = *(const float4*)(src + 4 * i);
            v.x *= cs; v.y *= cs; v.z *= cs; v.w *= cs;
            const uint32_t bx = __float_as_uint(v.x), by = __float_as_uint(v.y);
            const uint32_t bz = __float_as_uint(v.z), bw = __float_as_uint(v.w);
            dh[2 * i]     = prmt_hi(bx, by);
            dh[2 * i + 1] = prmt_hi(bz, bw);
            dl[2 * i]     = cvt_bf16x2(v.y - __uint_as_float(by & 0xffff0000u),
                                       v.x - __uint_as_float(bx & 0xffff0000u));
            dl[2 * i + 1] = cvt_bf16x2(v.w - __uint_as_float(bw & 0xffff0000u),
                                       v.z - __uint_as_float(bz & 0xffff0000u));
        }
    }

    float m0r = -1e30f, m1r = -1e30f, l0 = 0.f, l1 = 0.f;
    float oacc[8][4];
#pragma unroll
    for (int n = 0; n < 8; n++)
#pragma unroll
        for (int r = 0; r < 4; r++) oacc[n][r] = 0.f;

    __syncthreads();

    const int row_max_w = q0 + wid * 16 + 15;
    const int ntiles = 2 * qt + 2;

#pragma unroll 1
    for (int t = 0; t < ntiles; t++) {
        const int j0 = t * 64;

        {
            const int r = tid >> 2, hb2 = (tid & 3) * 16;
            const float* src = Kg + (size_t)(j0 + r) * 64 + hb2;
            uint32_t* dh = kh + r * STR + (hb2 >> 1);
            uint32_t* dl = kl + r * STR + (hb2 >> 1);
#pragma unroll
            for (int i = 0; i < 4; i++) {
                const float4 v = *(const float4*)(src + 4 * i);
                const uint32_t bx = __float_as_uint(v.x), by = __float_as_uint(v.y);
                const uint32_t bz = __float_as_uint(v.z), bw = __float_as_uint(v.w);
                dh[2 * i]     = prmt_hi(bx, by);
                dh[2 * i + 1] = prmt_hi(bz, bw);
                dl[2 * i]     = cvt_bf16x2(v.y - __uint_as_float(by & 0xffff0000u),
                                           v.x - __uint_as_float(bx & 0xffff0000u));
                dl[2 * i + 1] = cvt_bf16x2(v.w - __uint_as_float(bw & 0xffff0000u),
                                           v.z - __uint_as_float(bz & 0xffff0000u));
            }
        }
        {
            const int d = tid >> 2, kb = (tid & 3) * 16;
            const float* src = Vtg + (size_t)d * S_ + j0 + kb;
            uint32_t* dh = vh + d * STR + (kb >> 1);
            uint32_t* dl = vl + d * STR + (kb >> 1);
#pragma unroll
            for (int i = 0; i < 4; i++) {
                const float4 v = *(const float4*)(src + 4 * i);
                const uint32_t bx = __float_as_uint(v.x), by = __float_as_uint(v.y);
                const uint32_t bz = __float_as_uint(v.z), bw = __float_as_uint(v.w);
                dh[2 * i]     = prmt_hi(bx, by);
                dh[2 * i + 1] = prmt_hi(bz, bw);
                dl[2 * i]     = cvt_bf16x2(v.y - __uint_as_float(by & 0xffff0000u),
                                           v.x - __uint_as_float(bx & 0xffff0000u));
                dl[2 * i + 1] = cvt_bf16x2(v.w - __uint_as_float(bw & 0xffff0000u),
                                           v.z - __uint_as_float(bz & 0xffff0000u));
            }
        }
        __syncthreads();

        if (row_max_w >= j0) {
            float sacc[8][4];
#pragma unroll
            for (int n = 0; n < 8; n++)
#pragma unroll
                for (int r = 0; r < 4; r++) sacc[n][r] = 0.f;

#pragma unroll
            for (int jj = 0; jj < 4; jj++) {
                const int ab = (wid * 16 + grp) * STR + 8 * jj + tig;
                const uint32_t ah0 = qh[ab];
                const uint32_t ah1 = qh[ab + 8 * STR];
                const uint32_t ah2 = qh[ab + 4];
                const uint32_t ah3 = qh[ab + 8 * STR + 4];
                const uint32_t al0 = ql[ab];
                const uint32_t al1 = ql[ab + 8 * STR];
                const uint32_t al2 = ql[ab + 4];
                const uint32_t al3 = ql[ab + 8 * STR + 4];
#pragma unroll
                for (int n = 0; n < 8; n++) {
                    const int kb = (8 * n + grp) * STR + 8 * jj + tig;
                    const uint32_t bh0 = kh[kb], bh1 = kh[kb + 4];
                    const uint32_t bl0 = kl[kb], bl1 = kl[kb + 4];
                    mma_bf16(sacc[n][0], sacc[n][1], sacc[n][2], sacc[n][3],
                             ah0, ah1, ah2, ah3, bh0, bh1);
                    mma_bf16(sacc[n][0], sacc[n][1], sacc[n][2], sacc[n][3],
                             ah0, ah1, ah2, ah3, bl0, bl1);
                    mma_bf16(sacc[n][0], sacc[n][1], sacc[n][2], sacc[n][3],
                             al0, al1, al2, al3, bh0, bh1);
                }
            }

            const int row0 = q0 + wid * 16 + grp;
            const int row1 = row0 + 8;
            if (j0 + 63 > q0) {
#pragma unroll
                for (int n = 0; n < 8; n++) {
                    const int c = j0 + 8 * n + tig * 2;
                    if (c > row0)     sacc[n][0] = -1e30f;
                    if (c + 1 > row0) sacc[n][1] = -1e30f;
                    if (c > row1)     sacc[n][2] = -1e30f;
                    if (c + 1 > row1) sacc[n][3] = -1e30f;
                }
            }

            float mx0 = -1e30f, mx1 = -1e30f;
#pragma unroll
            for (int n = 0; n < 8; n++) {
                mx0 = fmaxf(mx0, fmaxf(sacc[n][0], sacc[n][1]));
                mx1 = fmaxf(mx1, fmaxf(sacc[n][2], sacc[n][3]));
            }
            mx0 = fmaxf(mx0, __shfl_xor_sync(0xffffffffu, mx0, 1));
            mx0 = fmaxf(mx0, __shfl_xor_sync(0xffffffffu, mx0, 2));
            mx1 = fmaxf(mx1, __shfl_xor_sync(0xffffffffu, mx1, 1));
            mx1 = fmaxf(mx1, __shfl_xor_sync(0xffffffffu, mx1, 2));

            const float mn0 = fmaxf(m0r, mx0);
            const float mn1 = fmaxf(m1r, mx1);
            const float fi0 = ex2_(m0r - mn0);
            const float fi1 = ex2_(m1r - mn1);
            m0r = mn0; m1r = mn1;

            float sum0 = 0.f, sum1 = 0.f;
#pragma unroll
            for (int n = 0; n < 8; n++) {
                sacc[n][0] = ex2_(sacc[n][0] - mn0);
                sacc[n][1] = ex2_(sacc[n][1] - mn0);
                sacc[n][2] = ex2_(sacc[n][2] - mn1);
                sacc[n][3] = ex2_(sacc[n][3] - mn1);
                sum0 += sacc[n][0] + sacc[n][1];
                sum1 += sacc[n][2] + sacc[n][3];
            }
            sum0 += __shfl_xor_sync(0xffffffffu, sum0, 1);
            sum0 += __shfl_xor_sync(0xffffffffu, sum0, 2);
            sum1 += __shfl_xor_sync(0xffffffffu, sum1, 1);
            sum1 += __shfl_xor_sync(0xffffffffu, sum1, 2);
            l0 = l0 * fi0 + sum0;
            l1 = l1 * fi1 + sum1;

#pragma unroll
            for (int n = 0; n < 8; n++) {
                oacc[n][0] *= fi0; oacc[n][1] *= fi0;
                oacc[n][2] *= fi1; oacc[n][3] *= fi1;
            }

#pragma unroll
            for (int jj = 0; jj < 4; jj++) {
                const uint32_t p00 = __float_as_uint(sacc[2 * jj][0]);
                const uint32_t p01 = __float_as_uint(sacc[2 * jj][1]);
                const uint32_t p02 = __float_as_uint(sacc[2 * jj][2]);
                const uint32_t p03 = __float_as_uint(sacc[2 * jj][3]);
                const uint32_t p10 = __float_as_uint(sacc[2 * jj + 1][0]);
                const uint32_t p11 = __float_as_uint(sacc[2 * jj + 1][1]);
                const uint32_t p12 = __float_as_uint(sacc[2 * jj + 1][2]);
                const uint32_t p13 = __float_as_uint(sacc[2 * jj + 1][3]);

                const uint32_t ph0 = prmt_hi(p00, p01);
                const uint32_t ph1 = prmt_hi(p02, p03);
                const uint32_t ph2 = prmt_hi(p10, p11);
                const uint32_t ph3 = prmt_hi(p12, p13);
                const uint32_t pl0 = cvt_bf16x2(
                    sacc[2 * jj][1] - __uint_as_float(p01 & 0xffff0000u),
                    sacc[2 * jj][0] - __uint_as_float(p00 & 0xffff0000u));
                const uint32_t pl1 = cvt_bf16x2(
                    sacc[2 * jj][3] - __uint_as_float(p03 & 0xffff0000u),
                    sacc[2 * jj][2] - __uint_as_float(p02 & 0xffff0000u));
                const uint32_t pl2 = cvt_bf16x2(
                    sacc[2 * jj + 1][1] - __uint_as_float(p11 & 0xffff0000u),
                    sacc[2 * jj + 1][0] - __uint_as_float(p10 & 0xffff0000u));
                const uint32_t pl3 = cvt_bf16x2(
                    sacc[2 * jj + 1][3] - __uint_as_float(p13 & 0xffff0000u),
                    sacc[2 * jj + 1][2] - __uint_as_float(p12 & 0xffff0000u));

#pragma unroll
                for (int n = 0; n < 8; n++) {
                    const int vb = (8 * n + grp) * STR + 8 * jj + tig;
                    const uint32_t bh0 = vh[vb], bh1 = vh[vb + 4];
                    const uint32_t bl0 = vl[vb], bl1 = vl[vb + 4];
                    mma_bf16(oacc[n][0], oacc[n][1], oacc[n][2], oacc[n][3],
                             ph0, ph1, ph2, ph3, bh0, bh1);
                    mma_bf16(oacc[n][0], oacc[n][1], oacc[n][2], oacc[n][3],
                             ph0, ph1, ph2, ph3, bl0, bl1);
                    mma_bf16(oacc[n][0], oacc[n][1], oacc[n][2], oacc[n][3],
                             pl0, pl1, pl2, pl3, bh0, bh1);
                }
            }
        }
        __syncthreads();
    }

    const float inv0 = 1.f / l0;
    const float inv1 = 1.f / l1;
    const int row0 = q0 + wid * 16 + grp;
#pragma unroll
    for (int n = 0; n < 8; n++) {
        const int col = h * 64 + 8 * n + tig * 2;
        *(float2*)&g_ctx[(size_t)(b * S_ + row0) * D_ + col] =
            make_float2(oacc[n][0] * inv0, oacc[n][1] * inv0);
        *(float2*)&g_ctx[(size_t)(b * S_ + row0 + 8) * D_ + col] =
            make_float2(oacc[n][2] * inv1, oacc[n][3] * inv1);
    }
}

// ---------------------------------------------------------------------------
extern "C" void kernel_launch(void* const* d_in, const int* in_sizes, int n_in,
                              void* d_out, int out_size) {
    const float* x      = (const float*)d_in[0];
    const float* W_attn = (const float*)d_in[1];
    const float* b_attn = (const float*)d_in[2];
    const float* W_proj = (const float*)d_in[3];
    const float* b_proj = (const float*)d_in[4];
    float* out = (float*)d_out;

    const int flash_smem = (128 * STR * 2 + 64 * STR * 4) * (int)sizeof(uint32_t); // 73728
    cudaFuncSetAttribute(flash_tc, cudaFuncAttributeMaxDynamicSharedMemorySize,
                         flash_smem);

    tc_gemm<3072, 0><<<dim3(3072 / 128, 8192 / 256), 256>>>(x, W_attn, b_attn, nullptr);
    flash_tc<<<dim3(S_ / 128, H_, B_), 256, flash_smem>>>();
    tc_gemm<1024, 1><<<dim3(1024 / 128, 8192 / 256), 256>>>(nullptr, W_proj, b_proj, out);
}

// round 11
// speedup vs baseline: 2.5179x; 1.0251x over previous
#include <cuda_runtime.h>
#include <cuda_bf16.h>
#include <math.h>
#include <stdint.h>

#define B_  4
#define S_  2048
#define D_  1024
#define H_  16
#define HD_ 64

// Scratch (allocation-free rule). Referenced ONLY from device code.
// g_qkv[0]: Q [b,h][s][hd]  g_qkv[1]: K [b,h][s][hd]  g_qkv[2]: V^T [b,h][hd][s]
__device__ float g_qkv[3][(size_t)B_ * H_ * S_ * HD_];
__device__ float g_ctx[(size_t)B_ * S_ * D_];

// ---------------------------------------------------------------------------
// helpers
// ---------------------------------------------------------------------------
__device__ __forceinline__ uint32_t prmt_hi(uint32_t a, uint32_t b) {
    uint32_t d;
    asm("prmt.b32 %0, %1, %2, 0x7632;" : "=r"(d) : "r"(a), "r"(b));
    return d;
}
__device__ __forceinline__ uint32_t cvt_bf16x2(float hi_val, float lo_val) {
    uint32_t d;
    asm("cvt.rn.bf16x2.f32 %0, %1, %2;" : "=r"(d) : "f"(hi_val), "f"(lo_val));
    return d;
}
__device__ __forceinline__ float ex2_(float x) {
    float y;
    asm("ex2.approx.ftz.f32 %0, %1;" : "=f"(y) : "f"(x));
    return y;
}
__device__ __forceinline__ void mma_bf16(float& c0, float& c1, float& c2, float& c3,
                                         uint32_t a0, uint32_t a1, uint32_t a2, uint32_t a3,
                                         uint32_t b0, uint32_t b1) {
    asm volatile(
        "mma.sync.aligned.m16n8k16.row.col.f32.bf16.bf16.f32 "
        "{%0,%1,%2,%3},{%4,%5,%6,%7},{%8,%9},{%0,%1,%2,%3};"
        : "+f"(c0), "+f"(c1), "+f"(c2), "+f"(c3)
        : "r"(a0), "r"(a1), "r"(a2), "r"(a3), "r"(b0), "r"(b1));
}

#define SROW 12
// stage layout (words): Ah[3072] Al[3072] Bh[1536] Bl[1536] = 9216 words/stage
#define ST_AL 3072
#define ST_BH 6144
#define ST_BL 7680
#define ST_WORDS 9216

__device__ __forceinline__ void split_store_row(uint32_t* Hh, uint32_t* Hl, int idx, float4 v) {
    const uint32_t bx = __float_as_uint(v.x), by = __float_as_uint(v.y);
    const uint32_t bz = __float_as_uint(v.z), bw = __float_as_uint(v.w);
    Hh[idx]     = prmt_hi(bx, by);
    Hh[idx + 1] = prmt_hi(bz, bw);
    Hl[idx]     = cvt_bf16x2(v.y - __uint_as_float(by & 0xffff0000u),
                             v.x - __uint_as_float(bx & 0xffff0000u));
    Hl[idx + 1] = cvt_bf16x2(v.w - __uint_as_float(bw & 0xffff0000u),
                             v.z - __uint_as_float(bz & 0xffff0000u));
}

__device__ __forceinline__ void stage_A(uint32_t* st, int am0, int ak2,
                                        float4 p0, float4 p1, float4 p2, float4 p3) {
    split_store_row(st, st + ST_AL, (am0 + 0) * SROW + ak2, p0);
    split_store_row(st, st + ST_AL, (am0 + 64) * SROW + ak2, p1);
    split_store_row(st, st + ST_AL, (am0 + 128) * SROW + ak2, p2);
    split_store_row(st, st + ST_AL, (am0 + 192) * SROW + ak2, p3);
}
__device__ __forceinline__ void stage_B(uint32_t* st, int bn4, int bk2,
                                        float4 v0, float4 v1) {
    uint32_t* BhS = st + ST_BH;
    uint32_t* BlS = st + ST_BL;
    const float e[4] = {v0.x, v0.y, v0.z, v0.w};
    const float o[4] = {v1.x, v1.y, v1.z, v1.w};
#pragma unroll
    for (int j = 0; j < 4; j++) {
        const uint32_t be = __float_as_uint(e[j]), bo = __float_as_uint(o[j]);
        BhS[(bn4 + j) * SROW + bk2] = prmt_hi(be, bo);
        BlS[(bn4 + j) * SROW + bk2] =
            cvt_bf16x2(o[j] - __uint_as_float(bo & 0xffff0000u),
                       e[j] - __uint_as_float(be & 0xffff0000u));
    }
}

// ---------------------------------------------------------------------------
// Kernel 1/3: tensor-core GEMM v3 — double-buffered smem, 1 sync per k-tile.
// Block 256x128, 8 warps (4M x 2N), warp tile 64x64, split-3 bf16.
// ---------------------------------------------------------------------------
template <int LDN, int MODE>
__global__ __launch_bounds__(256) void tc_gemm(const float* __restrict__ Xarg,
                                               const float* __restrict__ W,
                                               const float* __restrict__ bias,
                                               float* __restrict__ out) {
    extern __shared__ uint32_t smg[];   // 2 x 36KB stages

    const float* __restrict__ X = (MODE == 0) ? Xarg : (const float*)g_ctx;

    const int tid = threadIdx.x;
    const int lane = tid & 31;
    const int wid = tid >> 5;
    const int wm = wid >> 1;
    const int wn = wid & 1;
    const int grp = lane >> 2;
    const int tig = lane & 3;
    const int m0 = blockIdx.y * 256;
    const int n0 = blockIdx.x * 128;

    float acc[4][8][4];
#pragma unroll
    for (int mi = 0; mi < 4; mi++)
#pragma unroll
        for (int ni = 0; ni < 8; ni++)
#pragma unroll
            for (int r = 0; r < 4; r++) acc[mi][ni][r] = 0.f;

    const int am0 = tid >> 2;
    const int ak2 = (tid & 3) * 2;
    const int bk2 = tid & 7;
    const int bn4 = (tid >> 3) * 4;

    const int a_base = (wm * 64 + grp) * SROW + tig;
    const int b_base = (wn * 64 + grp) * SROW + tig;

    const float* Xp = X + (size_t)(m0 + am0) * 1024 + ak2 * 2;
    const float* Wp0 = W + (size_t)(2 * bk2) * LDN + n0 + bn4;
    const float* Wp1 = W + (size_t)(2 * bk2 + 1) * LDN + n0 + bn4;

    // ---- prologue: load tile 0, stage into buffer 0 ----
    float4 a_pre0 = *(const float4*)(Xp);
    float4 a_pre1 = *(const float4*)(Xp + (size_t)64 * 1024);
    float4 a_pre2 = *(const float4*)(Xp + (size_t)128 * 1024);
    float4 a_pre3 = *(const float4*)(Xp + (size_t)192 * 1024);
    float4 b_pre0 = *(const float4*)(Wp0);
    float4 b_pre1 = *(const float4*)(Wp1);
    stage_A(smg, am0, ak2, a_pre0, a_pre1, a_pre2, a_pre3);
    stage_B(smg, bn4, bk2, b_pre0, b_pre1);
    __syncthreads();

#pragma unroll 1
    for (int kt = 0; kt < 1024; kt += 16) {
        const int cur = (kt >> 4) & 1;
        uint32_t* stC = smg + cur * ST_WORDS;
        const bool hn = (kt + 16) < 1024;

        // ---- issue global prefetch for next k-tile ----
        if (hn) {
            const float* xp = Xp + kt + 16;
            a_pre0 = *(const float4*)(xp);
            a_pre1 = *(const float4*)(xp + (size_t)64 * 1024);
            a_pre2 = *(const float4*)(xp + (size_t)128 * 1024);
            a_pre3 = *(const float4*)(xp + (size_t)192 * 1024);
            b_pre0 = *(const float4*)(Wp0 + (size_t)(kt + 16) * LDN);
            b_pre1 = *(const float4*)(Wp1 + (size_t)(kt + 16) * LDN);
        }

        // ---- fragments + MMA from current stage ----
        const uint32_t* AhC = stC;
        const uint32_t* AlC = stC + ST_AL;
        const uint32_t* BhC = stC + ST_BH;
        const uint32_t* BlC = stC + ST_BL;

        uint32_t bh[8][2], bl[8][2];
#pragma unroll
        for (int ni = 0; ni < 8; ni++) {
            const int bb = b_base + ni * 8 * SROW;
            bh[ni][0] = BhC[bb]; bh[ni][1] = BhC[bb + 4];
            bl[ni][0] = BlC[bb]; bl[ni][1] = BlC[bb + 4];
        }

#pragma unroll
        for (int mi = 0; mi < 4; mi++) {
            const int ab = a_base + mi * 16 * SROW;
            const uint32_t ah0 = AhC[ab];
            const uint32_t ah1 = AhC[ab + 8 * SROW];
            const uint32_t ah2 = AhC[ab + 4];
            const uint32_t ah3 = AhC[ab + 8 * SROW + 4];
            const uint32_t al0 = AlC[ab];
            const uint32_t al1 = AlC[ab + 8 * SROW];
            const uint32_t al2 = AlC[ab + 4];
            const uint32_t al3 = AlC[ab + 8 * SROW + 4];
#pragma unroll
            for (int ni = 0; ni < 8; ni++) {
                mma_bf16(acc[mi][ni][0], acc[mi][ni][1], acc[mi][ni][2], acc[mi][ni][3],
                         ah0, ah1, ah2, ah3, bh[ni][0], bh[ni][1]);
                mma_bf16(acc[mi][ni][0], acc[mi][ni][1], acc[mi][ni][2], acc[mi][ni][3],
                         ah0, ah1, ah2, ah3, bl[ni][0], bl[ni][1]);
                mma_bf16(acc[mi][ni][0], acc[mi][ni][1], acc[mi][ni][2], acc[mi][ni][3],
                         al0, al1, al2, al3, bh[ni][0], bh[ni][1]);
            }
        }

        // ---- stage next tile into the other buffer (overlaps; guarded by sync) ----
        if (hn) {
            uint32_t* stN = smg + (cur ^ 1) * ST_WORDS;
            stage_A(stN, am0, ak2, a_pre0, a_pre1, a_pre2, a_pre3);
            stage_B(stN, bn4, bk2, b_pre0, b_pre1);
        }
        __syncthreads();
    }

    // ---- epilogue ----
#pragma unroll
    for (int mi = 0; mi < 4; mi++) {
#pragma unroll
        for (int rr = 0; rr < 2; rr++) {
            const int row = m0 + wm * 64 + mi * 16 + grp + rr * 8;
#pragma unroll
            for (int ni = 0; ni < 8; ni++) {
                const int n = n0 + wn * 64 + ni * 8 + tig * 2;
                const float v0 = acc[mi][ni][rr * 2 + 0] + bias[n];
                const float v1 = acc[mi][ni][rr * 2 + 1] + bias[n + 1];
                if (MODE == 0) {
                    const int b = row >> 11, s = row & 2047;
                    const int part = n >> 10;
                    const int d1 = n & 1023;
                    const int h = d1 >> 6, hd = d1 & 63;
                    if (part == 2) {
                        float* p = &g_qkv[2][((size_t)(b * H_ + h) * HD_ + hd) * S_ + s];
                        p[0] = v0;
                        p[S_] = v1;
                    } else {
                        float* p = &g_qkv[part][((size_t)(b * H_ + h) * S_ + s) * HD_ + hd];
                        *(float2*)p = make_float2(v0, v1);
                    }
                } else {
                    *(float2*)(out + (size_t)row * 1024 + n) = make_float2(v0, v1);
                }
            }
        }
    }
}

// ---------------------------------------------------------------------------
// Kernel 2: tensor-core flash attention (FROZEN from R8-passing).
// ---------------------------------------------------------------------------
#define STR 36

__global__ __launch_bounds__(256) void flash_tc() {
    extern __shared__ uint32_t sm4[];
    uint32_t* qh = sm4;
    uint32_t* ql = qh + 128 * STR;
    uint32_t* kh = ql + 128 * STR;
    uint32_t* kl = kh + 64 * STR;
    uint32_t* vh = kl + 64 * STR;
    uint32_t* vl = vh + 64 * STR;

    const int tid = threadIdx.x;
    const int lane = tid & 31;
    const int wid = tid >> 5;
    const int grp = lane >> 2;
    const int tig = lane & 3;
    const int qt = gridDim.x - 1 - blockIdx.x;
    const int q0 = qt * 128;
    const int h = blockIdx.y, b = blockIdx.z;

    const float* Qg  = g_qkv[0] + (size_t)(b * H_ + h) * S_ * HD_;
    const float* Kg  = g_qkv[1] + (size_t)(b * H_ + h) * S_ * HD_;
    const float* Vtg = g_qkv[2] + (size_t)(b * H_ + h) * HD_ * S_;

    {
        const float cs = 0.125f * 1.4426950408889634f;
        const int r = tid >> 1, hb = (tid & 1) * 32;
        const float* src = Qg + (size_t)(q0 + r) * 64 + hb;
        uint32_t* dh = qh + r * STR + (hb >> 1);
        uint32_t* dl = ql + r * STR + (hb >> 1);
#pragma unroll
        for (int i = 0; i < 8; i++) {
            float4 v = *(const float4*)(src + 4 * i);
            v.x *= cs; v.y *= cs; v.z *= cs; v.w *= cs;
            const uint32_t bx = __float_as_uint(v.x), by = __float_as_uint(v.y);
            const uint32_t bz = __float_as_uint(v.z), bw = __float_as_uint(v.w);
            dh[2 * i]     = prmt_hi(bx, by);
            dh[2 * i + 1] = prmt_hi(bz, bw);
            dl[2 * i]     = cvt_bf16x2(v.y - __uint_as_float(by & 0xffff0000u),
                                       v.x - __uint_as_float(bx & 0xffff0000u));
            dl[2 * i + 1] = cvt_bf16x2(v.w - __uint_as_float(bw & 0xffff0000u),
                                       v.z - __uint_as_float(bz & 0xffff0000u));
        }
    }

    float m0r = -1e30f, m1r = -1e30f, l0 = 0.f, l1 = 0.f;
    float oacc[8][4];
#pragma unroll
    for (int n = 0; n < 8; n++)
#pragma unroll
        for (int r = 0; r < 4; r++) oacc[n][r] = 0.f;

    __syncthreads();

    const int row_max_w = q0 + wid * 16 + 15;
    const int ntiles = 2 * qt + 2;

#pragma unroll 1
    for (int t = 0; t < ntiles; t++) {
        const int j0 = t * 64;

        {
            const int r = tid >> 2, hb2 = (tid & 3) * 16;
            const float* src = Kg + (size_t)(j0 + r) * 64 + hb2;
            uint32_t* dh = kh + r * STR + (hb2 >> 1);
            uint32_t* dl = kl + r * STR + (hb2 >> 1);
#pragma unroll
            for (int i = 0; i < 4; i++) {
                const float4 v = *(const float4*)(src + 4 * i);
                const uint32_t bx = __float_as_uint(v.x), by = __float_as_uint(v.y);
                const uint32_t bz = __float_as_uint(v.z), bw = __float_as_uint(v.w);
                dh[2 * i]     = prmt_hi(bx, by);
                dh[2 * i + 1] = prmt_hi(bz, bw);
                dl[2 * i]     = cvt_bf16x2(v.y - __uint_as_float(by & 0xffff0000u),
                                           v.x - __uint_as_float(bx & 0xffff0000u));
                dl[2 * i + 1] = cvt_bf16x2(v.w - __uint_as_float(bw & 0xffff0000u),
                                           v.z - __uint_as_float(bz & 0xffff0000u));
            }
        }
        {
            const int d = tid >> 2, kb = (tid & 3) * 16;
            const float* src = Vtg + (size_t)d * S_ + j0 + kb;
            uint32_t* dh = vh + d * STR + (kb >> 1);
            uint32_t* dl = vl + d * STR + (kb >> 1);
#pragma unroll
            for (int i = 0; i < 4; i++) {
                const float4 v = *(const float4*)(src + 4 * i);
                const uint32_t bx = __float_as_uint(v.x), by = __float_as_uint(v.y);
                const uint32_t bz = __float_as_uint(v.z), bw = __float_as_uint(v.w);
                dh[2 * i]     = prmt_hi(bx, by);
                dh[2 * i + 1] = prmt_hi(bz, bw);
                dl[2 * i]     = cvt_bf16x2(v.y - __uint_as_float(by & 0xffff0000u),
                                           v.x - __uint_as_float(bx & 0xffff0000u));
                dl[2 * i + 1] = cvt_bf16x2(v.w - __uint_as_float(bw & 0xffff0000u),
                                           v.z - __uint_as_float(bz & 0xffff0000u));
            }
        }
        __syncthreads();

        if (row_max_w >= j0) {
            float sacc[8][4];
#pragma unroll
            for (int n = 0; n < 8; n++)
#pragma unroll
                for (int r = 0; r < 4; r++) sacc[n][r] = 0.f;

#pragma unroll
            for (int jj = 0; jj < 4; jj++) {
                const int ab = (wid * 16 + grp) * STR + 8 * jj + tig;
                const uint32_t ah0 = qh[ab];
                const uint32_t ah1 = qh[ab + 8 * STR];
                const uint32_t ah2 = qh[ab + 4];
                const uint32_t ah3 = qh[ab + 8 * STR + 4];
                const uint32_t al0 = ql[ab];
                const uint32_t al1 = ql[ab + 8 * STR];
                const uint32_t al2 = ql[ab + 4];
                const uint32_t al3 = ql[ab + 8 * STR + 4];
#pragma unroll
                for (int n = 0; n < 8; n++) {
                    const int kb = (8 * n + grp) * STR + 8 * jj + tig;
                    const uint32_t bh0 = kh[kb], bh1 = kh[kb + 4];
                    const uint32_t bl0 = kl[kb], bl1 = kl[kb + 4];
                    mma_bf16(sacc[n][0], sacc[n][1], sacc[n][2], sacc[n][3],
                             ah0, ah1, ah2, ah3, bh0, bh1);
                    mma_bf16(sacc[n][0], sacc[n][1], sacc[n][2], sacc[n][3],
                             ah0, ah1, ah2, ah3, bl0, bl1);
                    mma_bf16(sacc[n][0], sacc[n][1], sacc[n][2], sacc[n][3],
                             al0, al1, al2, al3, bh0, bh1);
                }
            }

            const int row0 = q0 + wid * 16 + grp;
            const int row1 = row0 + 8;
            if (j0 + 63 > q0) {
#pragma unroll
                for (int n = 0; n < 8; n++) {
                    const int c = j0 + 8 * n + tig * 2;
                    if (c > row0)     sacc[n][0] = -1e30f;
                    if (c + 1 > row0) sacc[n][1] = -1e30f;
                    if (c > row1)     sacc[n][2] = -1e30f;
                    if (c + 1 > row1) sacc[n][3] = -1e30f;
                }
            }

            float mx0 = -1e30f, mx1 = -1e30f;
#pragma unroll
            for (int n = 0; n < 8; n++) {
                mx0 = fmaxf(mx0, fmaxf(sacc[n][0], sacc[n][1]));
                mx1 = fmaxf(mx1, fmaxf(sacc[n][2], sacc[n][3]));
            }
            mx0 = fmaxf(mx0, __shfl_xor_sync(0xffffffffu, mx0, 1));
            mx0 = fmaxf(mx0, __shfl_xor_sync(0xffffffffu, mx0, 2));
            mx1 = fmaxf(mx1, __shfl_xor_sync(0xffffffffu, mx1, 1));
            mx1 = fmaxf(mx1, __shfl_xor_sync(0xffffffffu, mx1, 2));

            const float mn0 = fmaxf(m0r, mx0);
            const float mn1 = fmaxf(m1r, mx1);
            const float fi0 = ex2_(m0r - mn0);
            const float fi1 = ex2_(m1r - mn1);
            m0r = mn0; m1r = mn1;

            float sum0 = 0.f, sum1 = 0.f;
#pragma unroll
            for (int n = 0; n < 8; n++) {
                sacc[n][0] = ex2_(sacc[n][0] - mn0);
                sacc[n][1] = ex2_(sacc[n][1] - mn0);
                sacc[n][2] = ex2_(sacc[n][2] - mn1);
                sacc[n][3] = ex2_(sacc[n][3] - mn1);
                sum0 += sacc[n][0] + sacc[n][1];
                sum1 += sacc[n][2] + sacc[n][3];
            }
            sum0 += __shfl_xor_sync(0xffffffffu, sum0, 1);
            sum0 += __shfl_xor_sync(0xffffffffu, sum0, 2);
            sum1 += __shfl_xor_sync(0xffffffffu, sum1, 1);
            sum1 += __shfl_xor_sync(0xffffffffu, sum1, 2);
            l0 = l0 * fi0 + sum0;
            l1 = l1 * fi1 + sum1;

#pragma unroll
            for (int n = 0; n < 8; n++) {
                oacc[n][0] *= fi0; oacc[n][1] *= fi0;
                oacc[n][2] *= fi1; oacc[n][3] *= fi1;
            }

#pragma unroll
            for (int jj = 0; jj < 4; jj++) {
                const uint32_t p00 = __float_as_uint(sacc[2 * jj][0]);
                const uint32_t p01 = __float_as_uint(sacc[2 * jj][1]);
                const uint32_t p02 = __float_as_uint(sacc[2 * jj][2]);
                const uint32_t p03 = __float_as_uint(sacc[2 * jj][3]);
                const uint32_t p10 = __float_as_uint(sacc[2 * jj + 1][0]);
                const uint32_t p11 = __float_as_uint(sacc[2 * jj + 1][1]);
                const uint32_t p12 = __float_as_uint(sacc[2 * jj + 1][2]);
                const uint32_t p13 = __float_as_uint(sacc[2 * jj + 1][3]);

                const uint32_t ph0 = prmt_hi(p00, p01);
                const uint32_t ph1 = prmt_hi(p02, p03);
                const uint32_t ph2 = prmt_hi(p10, p11);
                const uint32_t ph3 = prmt_hi(p12, p13);
                const uint32_t pl0 = cvt_bf16x2(
                    sacc[2 * jj][1] - __uint_as_float(p01 & 0xffff0000u),
                    sacc[2 * jj][0] - __uint_as_float(p00 & 0xffff0000u));
                const uint32_t pl1 = cvt_bf16x2(
                    sacc[2 * jj][3] - __uint_as_float(p03 & 0xffff0000u),
                    sacc[2 * jj][2] - __uint_as_float(p02 & 0xffff0000u));
                const uint32_t pl2 = cvt_bf16x2(
                    sacc[2 * jj + 1][1] - __uint_as_float(p11 & 0xffff0000u),
                    sacc[2 * jj + 1][0] - __uint_as_float(p10 & 0xffff0000u));
                const uint32_t pl3 = cvt_bf16x2(
                    sacc[2 * jj + 1][3] - __uint_as_float(p13 & 0xffff0000u),
                    sacc[2 * jj + 1][2] - __uint_as_float(p12 & 0xffff0000u));

#pragma unroll
                for (int n = 0; n < 8; n++) {
                    const int vb = (8 * n + grp) * STR + 8 * jj + tig;
                    const uint32_t bh0 = vh[vb], bh1 = vh[vb + 4];
                    const uint32_t bl0 = vl[vb], bl1 = vl[vb + 4];
                    mma_bf16(oacc[n][0], oacc[n][1], oacc[n][2], oacc[n][3],
                             ph0, ph1, ph2, ph3, bh0, bh1);
                    mma_bf16(oacc[n][0], oacc[n][1], oacc[n][2], oacc[n][3],
                             ph0, ph1, ph2, ph3, bl0, bl1);
                    mma_bf16(oacc[n][0], oacc[n][1], oacc[n][2], oacc[n][3],
                             pl0, pl1, pl2, pl3, bh0, bh1);
                }
            }
        }
        __syncthreads();
    }

    const float inv0 = 1.f / l0;
    const float inv1 = 1.f / l1;
    const int row0 = q0 + wid * 16 + grp;
#pragma unroll
    for (int n = 0; n < 8; n++) {
        const int col = h * 64 + 8 * n + tig * 2;
        *(float2*)&g_ctx[(size_t)(b * S_ + row0) * D_ + col] =
            make_float2(oacc[n][0] * inv0, oacc[n][1] * inv0);
        *(float2*)&g_ctx[(size_t)(b * S_ + row0 + 8) * D_ + col] =
            make_float2(oacc[n][2] * inv1, oacc[n][3] * inv1);
    }
}

// ---------------------------------------------------------------------------
extern "C" void kernel_launch(void* const* d_in, const int* in_sizes, int n_in,
                              void* d_out, int out_size) {
    const float* x      = (const float*)d_in[0];
    const float* W_attn = (const float*)d_in[1];
    const float* b_attn = (const float*)d_in[2];
    const float* W_proj = (const float*)d_in[3];
    const float* b_proj = (const float*)d_in[4];
    float* out = (float*)d_out;

    const int gemm_smem = 2 * ST_WORDS * (int)sizeof(uint32_t);  // 73728
    cudaFuncSetAttribute(tc_gemm<3072, 0>, cudaFuncAttributeMaxDynamicSharedMemorySize,
                         gemm_smem);
    cudaFuncSetAttribute(tc_gemm<1024, 1>, cudaFuncAttributeMaxDynamicSharedMemorySize,
                         gemm_smem);

    const int flash_smem = (128 * STR * 2 + 64 * STR * 4) * (int)sizeof(uint32_t); // 73728
    cudaFuncSetAttribute(flash_tc, cudaFuncAttributeMaxDynamicSharedMemorySize,
                         flash_smem);

    tc_gemm<3072, 0><<<dim3(3072 / 128, 8192 / 256), 256, gemm_smem>>>(x, W_attn, b_attn, nullptr);
    flash_tc<<<dim3(S_ / 128, H_, B_), 256, flash_smem>>>();
    tc_gemm<1024, 1><<<dim3(1024 / 128, 8192 / 256), 256, gemm_smem>>>(nullptr, W_proj, b_proj, out);
}

// round 14
// speedup vs baseline: 2.7436x; 1.0896x over previous
#include <cuda_runtime.h>
#include <cuda_bf16.h>
#include <math.h>
#include <stdint.h>

#define B_  4
#define S_  2048
#define D_  1024
#define H_  16
#define HD_ 64

// Scratch (allocation-free rule). Referenced ONLY from device code.
// g_qkv[0]: Q [b,h][s][hd]  g_qkv[1]: K [b,h][s][hd]  g_qkv[2]: V^T [b,h][hd][s]
__device__ float g_qkv[3][(size_t)B_ * H_ * S_ * HD_];
__device__ float g_ctx[(size_t)B_ * S_ * D_];

// ---------------------------------------------------------------------------
// helpers
// ---------------------------------------------------------------------------
__device__ __forceinline__ uint32_t prmt_hi(uint32_t a, uint32_t b) {
    uint32_t d;
    asm("prmt.b32 %0, %1, %2, 0x7632;" : "=r"(d) : "r"(a), "r"(b));
    return d;
}
__device__ __forceinline__ uint32_t cvt_bf16x2(float hi_val, float lo_val) {
    uint32_t d;
    asm("cvt.rn.bf16x2.f32 %0, %1, %2;" : "=r"(d) : "f"(hi_val), "f"(lo_val));
    return d;
}
__device__ __forceinline__ float ex2_(float x) {
    float y;
    asm("ex2.approx.ftz.f32 %0, %1;" : "=f"(y) : "f"(x));
    return y;
}
__device__ __forceinline__ void mma_bf16(float& c0, float& c1, float& c2, float& c3,
                                         uint32_t a0, uint32_t a1, uint32_t a2, uint32_t a3,
                                         uint32_t b0, uint32_t b1) {
    asm volatile(
        "mma.sync.aligned.m16n8k16.row.col.f32.bf16.bf16.f32 "
        "{%0,%1,%2,%3},{%4,%5,%6,%7},{%8,%9},{%0,%1,%2,%3};"
        : "+f"(c0), "+f"(c1), "+f"(c2), "+f"(c3)
        : "r"(a0), "r"(a1), "r"(a2), "r"(a3), "r"(b0), "r"(b1));
}

#define SROW 12
// stage layout (words): Ah[3072] Al[3072] Bh[1536] Bl[1536] = 9216 words/stage
#define ST_AL 3072
#define ST_BH 6144
#define ST_BL 7680
#define ST_WORDS 9216

__device__ __forceinline__ void split_store_row(uint32_t* Hh, uint32_t* Hl, int idx, float4 v) {
    const uint32_t bx = __float_as_uint(v.x), by = __float_as_uint(v.y);
    const uint32_t bz = __float_as_uint(v.z), bw = __float_as_uint(v.w);
    Hh[idx]     = prmt_hi(bx, by);
    Hh[idx + 1] = prmt_hi(bz, bw);
    Hl[idx]     = cvt_bf16x2(v.y - __uint_as_float(by & 0xffff0000u),
                             v.x - __uint_as_float(bx & 0xffff0000u));
    Hl[idx + 1] = cvt_bf16x2(v.w - __uint_as_float(bw & 0xffff0000u),
                             v.z - __uint_as_float(bz & 0xffff0000u));
}

__device__ __forceinline__ void stage_A(uint32_t* st, int am0, int ak2,
                                        float4 p0, float4 p1, float4 p2, float4 p3) {
    split_store_row(st, st + ST_AL, (am0 + 0) * SROW + ak2, p0);
    split_store_row(st, st + ST_AL, (am0 + 64) * SROW + ak2, p1);
    split_store_row(st, st + ST_AL, (am0 + 128) * SROW + ak2, p2);
    split_store_row(st, st + ST_AL, (am0 + 192) * SROW + ak2, p3);
}
__device__ __forceinline__ void stage_B(uint32_t* st, int bn4, int bk2,
                                        float4 v0, float4 v1) {
    uint32_t* BhS = st + ST_BH;
    uint32_t* BlS = st + ST_BL;
    const float e[4] = {v0.x, v0.y, v0.z, v0.w};
    const float o[4] = {v1.x, v1.y, v1.z, v1.w};
#pragma unroll
    for (int j = 0; j < 4; j++) {
        const uint32_t be = __float_as_uint(e[j]), bo = __float_as_uint(o[j]);
        BhS[(bn4 + j) * SROW + bk2] = prmt_hi(be, bo);
        BlS[(bn4 + j) * SROW + bk2] =
            cvt_bf16x2(o[j] - __uint_as_float(bo & 0xffff0000u),
                       e[j] - __uint_as_float(be & 0xffff0000u));
    }
}

// ---------------------------------------------------------------------------
// Kernel 1/3: tensor-core GEMM — double-buffered smem (R11-passing), with
// PASS-MAJOR MMA ordering: consecutive HMMAs hit different accumulators so
// the pinned asm program order has no back-to-back dependency chains.
// ---------------------------------------------------------------------------
template <int LDN, int MODE>
__global__ __launch_bounds__(256) void tc_gemm(const float* __restrict__ Xarg,
                                               const float* __restrict__ W,
                                               const float* __restrict__ bias,
                                               float* __restrict__ out) {
    extern __shared__ uint32_t smg[];   // 2 x 36KB stages

    const float* __restrict__ X = (MODE == 0) ? Xarg : (const float*)g_ctx;

    const int tid = threadIdx.x;
    const int lane = tid & 31;
    const int wid = tid >> 5;
    const int wm = wid >> 1;
    const int wn = wid & 1;
    const int grp = lane >> 2;
    const int tig = lane & 3;
    const int m0 = blockIdx.y * 256;
    const int n0 = blockIdx.x * 128;

    float acc[4][8][4];
#pragma unroll
    for (int mi = 0; mi < 4; mi++)
#pragma unroll
        for (int ni = 0; ni < 8; ni++)
#pragma unroll
            for (int r = 0; r < 4; r++) acc[mi][ni][r] = 0.f;

    const int am0 = tid >> 2;
    const int ak2 = (tid & 3) * 2;
    const int bk2 = tid & 7;
    const int bn4 = (tid >> 3) * 4;

    const int a_base = (wm * 64 + grp) * SROW + tig;
    const int b_base = (wn * 64 + grp) * SROW + tig;

    const float* Xp = X + (size_t)(m0 + am0) * 1024 + ak2 * 2;
    const float* Wp0 = W + (size_t)(2 * bk2) * LDN + n0 + bn4;
    const float* Wp1 = W + (size_t)(2 * bk2 + 1) * LDN + n0 + bn4;

    // ---- prologue: load tile 0, stage into buffer 0 ----
    float4 a_pre0 = *(const float4*)(Xp);
    float4 a_pre1 = *(const float4*)(Xp + (size_t)64 * 1024);
    float4 a_pre2 = *(const float4*)(Xp + (size_t)128 * 1024);
    float4 a_pre3 = *(const float4*)(Xp + (size_t)192 * 1024);
    float4 b_pre0 = *(const float4*)(Wp0);
    float4 b_pre1 = *(const float4*)(Wp1);
    stage_A(smg, am0, ak2, a_pre0, a_pre1, a_pre2, a_pre3);
    stage_B(smg, bn4, bk2, b_pre0, b_pre1);
    __syncthreads();

#pragma unroll 1
    for (int kt = 0; kt < 1024; kt += 16) {
        const int cur = (kt >> 4) & 1;
        uint32_t* stC = smg + cur * ST_WORDS;
        const bool hn = (kt + 16) < 1024;

        // ---- issue global prefetch for next k-tile ----
        if (hn) {
            const float* xp = Xp + kt + 16;
            a_pre0 = *(const float4*)(xp);
            a_pre1 = *(const float4*)(xp + (size_t)64 * 1024);
            a_pre2 = *(const float4*)(xp + (size_t)128 * 1024);
            a_pre3 = *(const float4*)(xp + (size_t)192 * 1024);
            b_pre0 = *(const float4*)(Wp0 + (size_t)(kt + 16) * LDN);
            b_pre1 = *(const float4*)(Wp1 + (size_t)(kt + 16) * LDN);
        }

        const uint32_t* AhC = stC;
        const uint32_t* AlC = stC + ST_AL;
        const uint32_t* BhC = stC + ST_BH;
        const uint32_t* BlC = stC + ST_BL;

        uint32_t bh[8][2], bl[8][2];
#pragma unroll
        for (int ni = 0; ni < 8; ni++) {
            const int bb = b_base + ni * 8 * SROW;
            bh[ni][0] = BhC[bb]; bh[ni][1] = BhC[bb + 4];
            bl[ni][0] = BlC[bb]; bl[ni][1] = BlC[bb + 4];
        }

#pragma unroll
        for (int mi = 0; mi < 4; mi++) {
            const int ab = a_base + mi * 16 * SROW;
            const uint32_t ah0 = AhC[ab];
            const uint32_t ah1 = AhC[ab + 8 * SROW];
            const uint32_t ah2 = AhC[ab + 4];
            const uint32_t ah3 = AhC[ab + 8 * SROW + 4];
            const uint32_t al0 = AlC[ab];
            const uint32_t al1 = AlC[ab + 8 * SROW];
            const uint32_t al2 = AlC[ab + 4];
            const uint32_t al3 = AlC[ab + 8 * SROW + 4];

            // pass 1: Ah @ Bh over all ni (8 independent MMAs)
#pragma unroll
            for (int ni = 0; ni < 8; ni++)
                mma_bf16(acc[mi][ni][0], acc[mi][ni][1], acc[mi][ni][2], acc[mi][ni][3],
                         ah0, ah1, ah2, ah3, bh[ni][0], bh[ni][1]);
            // pass 2: Ah @ Bl
#pragma unroll
            for (int ni = 0; ni < 8; ni++)
                mma_bf16(acc[mi][ni][0], acc[mi][ni][1], acc[mi][ni][2], acc[mi][ni][3],
                         ah0, ah1, ah2, ah3, bl[ni][0], bl[ni][1]);
            // pass 3: Al @ Bh
#pragma unroll
            for (int ni = 0; ni < 8; ni++)
                mma_bf16(acc[mi][ni][0], acc[mi][ni][1], acc[mi][ni][2], acc[mi][ni][3],
                         al0, al1, al2, al3, bh[ni][0], bh[ni][1]);
        }

        // ---- stage next tile into the other buffer (guarded by sync) ----
        if (hn) {
            uint32_t* stN = smg + (cur ^ 1) * ST_WORDS;
            stage_A(stN, am0, ak2, a_pre0, a_pre1, a_pre2, a_pre3);
            stage_B(stN, bn4, bk2, b_pre0, b_pre1);
        }
        __syncthreads();
    }

    // ---- epilogue ----
#pragma unroll
    for (int mi = 0; mi < 4; mi++) {
#pragma unroll
        for (int rr = 0; rr < 2; rr++) {
            const int row = m0 + wm * 64 + mi * 16 + grp + rr * 8;
#pragma unroll
            for (int ni = 0; ni < 8; ni++) {
                const int n = n0 + wn * 64 + ni * 8 + tig * 2;
                const float v0 = acc[mi][ni][rr * 2 + 0] + bias[n];
                const float v1 = acc[mi][ni][rr * 2 + 1] + bias[n + 1];
                if (MODE == 0) {
                    const int b = row >> 11, s = row & 2047;
                    const int part = n >> 10;
                    const int d1 = n & 1023;
                    const int h = d1 >> 6, hd = d1 & 63;
                    if (part == 2) {
                        float* p = &g_qkv[2][((size_t)(b * H_ + h) * HD_ + hd) * S_ + s];
                        p[0] = v0;
                        p[S_] = v1;
                    } else {
                        float* p = &g_qkv[part][((size_t)(b * H_ + h) * S_ + s) * HD_ + hd];
                        *(float2*)p = make_float2(v0, v1);
                    }
                } else {
                    *(float2*)(out + (size_t)row * 1024 + n) = make_float2(v0, v1);
                }
            }
        }
    }
}

// ---------------------------------------------------------------------------
// Kernel 2: tensor-core flash attention — same pass-major MMA reordering.
// ---------------------------------------------------------------------------
#define STR 36

__global__ __launch_bounds__(256) void flash_tc() {
    extern __shared__ uint32_t sm4[];
    uint32_t* qh = sm4;
    uint32_t* ql = qh + 128 * STR;
    uint32_t* kh = ql + 128 * STR;
    uint32_t* kl = kh + 64 * STR;
    uint32_t* vh = kl + 64 * STR;
    uint32_t* vl = vh + 64 * STR;

    const int tid = threadIdx.x;
    const int lane = tid & 31;
    const int wid = tid >> 5;
    const int grp = lane >> 2;
    const int tig = lane & 3;
    const int qt = gridDim.x - 1 - blockIdx.x;
    const int q0 = qt * 128;
    const int h = blockIdx.y, b = blockIdx.z;

    const float* Qg  = g_qkv[0] + (size_t)(b * H_ + h) * S_ * HD_;
    const float* Kg  = g_qkv[1] + (size_t)(b * H_ + h) * S_ * HD_;
    const float* Vtg = g_qkv[2] + (size_t)(b * H_ + h) * HD_ * S_;

    {
        const float cs = 0.125f * 1.4426950408889634f;
        const int r = tid >> 1, hb = (tid & 1) * 32;
        const float* src = Qg + (size_t)(q0 + r) * 64 + hb;
        uint32_t* dh = qh + r * STR + (hb >> 1);
        uint32_t* dl = ql + r * STR + (hb >> 1);
#pragma unroll
        for (int i = 0; i < 8; i++) {
            float4 v = *(const float4*)(src + 4 * i);
            v.x *= cs; v.y *= cs; v.z *= cs; v.w *= cs;
            const uint32_t bx = __float_as_uint(v.x), by = __float_as_uint(v.y);
            const uint32_t bz = __float_as_uint(v.z), bw = __float_as_uint(v.w);
            dh[2 * i]     = prmt_hi(bx, by);
            dh[2 * i + 1] = prmt_hi(bz, bw);
            dl[2 * i]     = cvt_bf16x2(v.y - __uint_as_float(by & 0xffff0000u),
                                       v.x - __uint_as_float(bx & 0xffff0000u));
            dl[2 * i + 1] = cvt_bf16x2(v.w - __uint_as_float(bw & 0xffff0000u),
                                       v.z - __uint_as_float(bz & 0xffff0000u));
        }
    }

    float m0r = -1e30f, m1r = -1e30f, l0 = 0.f, l1 = 0.f;
    float oacc[8][4];
#pragma unroll
    for (int n = 0; n < 8; n++)
#pragma unroll
        for (int r = 0; r < 4; r++) oacc[n][r] = 0.f;

    __syncthreads();

    const int row_max_w = q0 + wid * 16 + 15;
    const int ntiles = 2 * qt + 2;

#pragma unroll 1
    for (int t = 0; t < ntiles; t++) {
        const int j0 = t * 64;

        {
            const int r = tid >> 2, hb2 = (tid & 3) * 16;
            const float* src = Kg + (size_t)(j0 + r) * 64 + hb2;
            uint32_t* dh = kh + r * STR + (hb2 >> 1);
            uint32_t* dl = kl + r * STR + (hb2 >> 1);
#pragma unroll
            for (int i = 0; i < 4; i++) {
                const float4 v = *(const float4*)(src + 4 * i);
                const uint32_t bx = __float_as_uint(v.x), by = __float_as_uint(v.y);
                const uint32_t bz = __float_as_uint(v.z), bw = __float_as_uint(v.w);
                dh[2 * i]     = prmt_hi(bx, by);
                dh[2 * i + 1] = prmt_hi(bz, bw);
                dl[2 * i]     = cvt_bf16x2(v.y - __uint_as_float(by & 0xffff0000u),
                                           v.x - __uint_as_float(bx & 0xffff0000u));
                dl[2 * i + 1] = cvt_bf16x2(v.w - __uint_as_float(bw & 0xffff0000u),
                                           v.z - __uint_as_float(bz & 0xffff0000u));
            }
        }
        {
            const int d = tid >> 2, kb = (tid & 3) * 16;
            const float* src = Vtg + (size_t)d * S_ + j0 + kb;
            uint32_t* dh = vh + d * STR + (kb >> 1);
            uint32_t* dl = vl + d * STR + (kb >> 1);
#pragma unroll
            for (int i = 0; i < 4; i++) {
                const float4 v = *(const float4*)(src + 4 * i);
                const uint32_t bx = __float_as_uint(v.x), by = __float_as_uint(v.y);
                const uint32_t bz = __float_as_uint(v.z), bw = __float_as_uint(v.w);
                dh[2 * i]     = prmt_hi(bx, by);
                dh[2 * i + 1] = prmt_hi(bz, bw);
                dl[2 * i]     = cvt_bf16x2(v.y - __uint_as_float(by & 0xffff0000u),
                                           v.x - __uint_as_float(bx & 0xffff0000u));
                dl[2 * i + 1] = cvt_bf16x2(v.w - __uint_as_float(bw & 0xffff0000u),
                                           v.z - __uint_as_float(bz & 0xffff0000u));
            }
        }
        __syncthreads();

        if (row_max_w >= j0) {
            float sacc[8][4];
#pragma unroll
            for (int n = 0; n < 8; n++)
#pragma unroll
                for (int r = 0; r < 4; r++) sacc[n][r] = 0.f;

#pragma unroll
            for (int jj = 0; jj < 4; jj++) {
                const int ab = (wid * 16 + grp) * STR + 8 * jj + tig;
                const uint32_t ah0 = qh[ab];
                const uint32_t ah1 = qh[ab + 8 * STR];
                const uint32_t ah2 = qh[ab + 4];
                const uint32_t ah3 = qh[ab + 8 * STR + 4];
                const uint32_t al0 = ql[ab];
                const uint32_t al1 = ql[ab + 8 * STR];
                const uint32_t al2 = ql[ab + 4];
                const uint32_t al3 = ql[ab + 8 * STR + 4];
                // pass-major: 8 independent MMAs per pass
#pragma unroll
                for (int n = 0; n < 8; n++) {
                    const int kb = (8 * n + grp) * STR + 8 * jj + tig;
                    mma_bf16(sacc[n][0], sacc[n][1], sacc[n][2], sacc[n][3],
                             ah0, ah1, ah2, ah3, kh[kb], kh[kb + 4]);
                }
#pragma unroll
                for (int n = 0; n < 8; n++) {
                    const int kb = (8 * n + grp) * STR + 8 * jj + tig;
                    mma_bf16(sacc[n][0], sacc[n][1], sacc[n][2], sacc[n][3],
                             ah0, ah1, ah2, ah3, kl[kb], kl[kb + 4]);
                }
#pragma unroll
                for (int n = 0; n < 8; n++) {
                    const int kb = (8 * n + grp) * STR + 8 * jj + tig;
                    mma_bf16(sacc[n][0], sacc[n][1], sacc[n][2], sacc[n][3],
                             al0, al1, al2, al3, kh[kb], kh[kb + 4]);
                }
            }

            const int row0 = q0 + wid * 16 + grp;
            const int row1 = row0 + 8;
            if (j0 + 63 > q0) {
#pragma unroll
                for (int n = 0; n < 8; n++) {
                    const int c = j0 + 8 * n + tig * 2;
                    if (c > row0)     sacc[n][0] = -1e30f;
                    if (c + 1 > row0) sacc[n][1] = -1e30f;
                    if (c > row1)     sacc[n][2] = -1e30f;
                    if (c + 1 > row1) sacc[n][3] = -1e30f;
                }
            }

            float mx0 = -1e30f, mx1 = -1e30f;
#pragma unroll
            for (int n = 0; n < 8; n++) {
                mx0 = fmaxf(mx0, fmaxf(sacc[n][0], sacc[n][1]));
                mx1 = fmaxf(mx1, fmaxf(sacc[n][2], sacc[n][3]));
            }
            mx0 = fmaxf(mx0, __shfl_xor_sync(0xffffffffu, mx0, 1));
            mx0 = fmaxf(mx0, __shfl_xor_sync(0xffffffffu, mx0, 2));
            mx1 = fmaxf(mx1, __shfl_xor_sync(0xffffffffu, mx1, 1));
            mx1 = fmaxf(mx1, __shfl_xor_sync(0xffffffffu, mx1, 2));

            const float mn0 = fmaxf(m0r, mx0);
            const float mn1 = fmaxf(m1r, mx1);
            const float fi0 = ex2_(m0r - mn0);
            const float fi1 = ex2_(m1r - mn1);
            m0r = mn0; m1r = mn1;

            float sum0 = 0.f, sum1 = 0.f;
#pragma unroll
            for (int n = 0; n < 8; n++) {
                sacc[n][0] = ex2_(sacc[n][0] - mn0);
                sacc[n][1] = ex2_(sacc[n][1] - mn0);
                sacc[n][2] = ex2_(sacc[n][2] - mn1);
                sacc[n][3] = ex2_(sacc[n][3] - mn1);
                sum0 += sacc[n][0] + sacc[n][1];
                sum1 += sacc[n][2] + sacc[n][3];
            }
            sum0 += __shfl_xor_sync(0xffffffffu, sum0, 1);
            sum0 += __shfl_xor_sync(0xffffffffu, sum0, 2);
            sum1 += __shfl_xor_sync(0xffffffffu, sum1, 1);
            sum1 += __shfl_xor_sync(0xffffffffu, sum1, 2);
            l0 = l0 * fi0 + sum0;
            l1 = l1 * fi1 + sum1;

#pragma unroll
            for (int n = 0; n < 8; n++) {
                oacc[n][0] *= fi0; oacc[n][1] *= fi0;
                oacc[n][2] *= fi1; oacc[n][3] *= fi1;
            }

            // ---- O += P @ V, pass-major across n ----
#pragma unroll
            for (int jj = 0; jj < 4; jj++) {
                const uint32_t p00 = __float_as_uint(sacc[2 * jj][0]);
                const uint32_t p01 = __float_as_uint(sacc[2 * jj][1]);
                const uint32_t p02 = __float_as_uint(sacc[2 * jj][2]);
                const uint32_t p03 = __float_as_uint(sacc[2 * jj][3]);
                const uint32_t p10 = __float_as_uint(sacc[2 * jj + 1][0]);
                const uint32_t p11 = __float_as_uint(sacc[2 * jj + 1][1]);
                const uint32_t p12 = __float_as_uint(sacc[2 * jj + 1][2]);
                const uint32_t p13 = __float_as_uint(sacc[2 * jj + 1][3]);

                const uint32_t ph0 = prmt_hi(p00, p01);
                const uint32_t ph1 = prmt_hi(p02, p03);
                const uint32_t ph2 = prmt_hi(p10, p11);
                const uint32_t ph3 = prmt_hi(p12, p13);
                const uint32_t pl0 = cvt_bf16x2(
                    sacc[2 * jj][1] - __uint_as_float(p01 & 0xffff0000u),
                    sacc[2 * jj][0] - __uint_as_float(p00 & 0xffff0000u));
                const uint32_t pl1 = cvt_bf16x2(
                    sacc[2 * jj][3] - __uint_as_float(p03 & 0xffff0000u),
                    sacc[2 * jj][2] - __uint_as_float(p02 & 0xffff0000u));
                const uint32_t pl2 = cvt_bf16x2(
                    sacc[2 * jj + 1][1] - __uint_as_float(p11 & 0xffff0000u),
                    sacc[2 * jj + 1][0] - __uint_as_float(p10 & 0xffff0000u));
                const uint32_t pl3 = cvt_bf16x2(
                    sacc[2 * jj + 1][3] - __uint_as_float(p13 & 0xffff0000u),
                    sacc[2 * jj + 1][2] - __uint_as_float(p12 & 0xffff0000u));

#pragma unroll
                for (int n = 0; n < 8; n++) {
                    const int vb = (8 * n + grp) * STR + 8 * jj + tig;
                    mma_bf16(oacc[n][0], oacc[n][1], oacc[n][2], oacc[n][3],
                             ph0, ph1, ph2, ph3, vh[vb], vh[vb + 4]);
                }
#pragma unroll
                for (int n = 0; n < 8; n++) {
                    const int vb = (8 * n + grp) * STR + 8 * jj + tig;
                    mma_bf16(oacc[n][0], oacc[n][1], oacc[n][2], oacc[n][3],
                             ph0, ph1, ph2, ph3, vl[vb], vl[vb + 4]);
                }
#pragma unroll
                for (int n = 0; n < 8; n++) {
                    const int vb = (8 * n + grp) * STR + 8 * jj + tig;
                    mma_bf16(oacc[n][0], oacc[n][1], oacc[n][2], oacc[n][3],
                             pl0, pl1, pl2, pl3, vh[vb], vh[vb + 4]);
                }
            }
        }
        __syncthreads();
    }

    const float inv0 = 1.f / l0;
    const float inv1 = 1.f / l1;
    const int row0 = q0 + wid * 16 + grp;
#pragma unroll
    for (int n = 0; n < 8; n++) {
        const int col = h * 64 + 8 * n + tig * 2;
        *(float2*)&g_ctx[(size_t)(b * S_ + row0) * D_ + col] =
            make_float2(oacc[n][0] * inv0, oacc[n][1] * inv0);
        *(float2*)&g_ctx[(size_t)(b * S_ + row0 + 8) * D_ + col] =
            make_float2(oacc[n][2] * inv1, oacc[n][3] * inv1);
    }
}

// ---------------------------------------------------------------------------
extern "C" void kernel_launch(void* const* d_in, const int* in_sizes, int n_in,
                              void* d_out, int out_size) {
    const float* x      = (const float*)d_in[0];
    const float* W_attn = (const float*)d_in[1];
    const float* b_attn = (const float*)d_in[2];
    const float* W_proj = (const float*)d_in[3];
    const float* b_proj = (const float*)d_in[4];
    float* out = (float*)d_out;

    const int gemm_smem = 2 * ST_WORDS * (int)sizeof(uint32_t);  // 73728
    cudaFuncSetAttribute(tc_gemm<3072, 0>, cudaFuncAttributeMaxDynamicSharedMemorySize,
                         gemm_smem);
    cudaFuncSetAttribute(tc_gemm<1024, 1>, cudaFuncAttributeMaxDynamicSharedMemorySize,
                         gemm_smem);

    const int flash_smem = (128 * STR * 2 + 64 * STR * 4) * (int)sizeof(uint32_t); // 73728
    cudaFuncSetAttribute(flash_tc, cudaFuncAttributeMaxDynamicSharedMemorySize,
                         flash_smem);

    tc_gemm<3072, 0><<<dim3(3072 / 128, 8192 / 256), 256, gemm_smem>>>(x, W_attn, b_attn, nullptr);
    flash_tc<<<dim3(S_ / 128, H_, B_), 256, flash_smem>>>();
    tc_gemm<1024, 1><<<dim3(1024 / 128, 8192 / 256), 256, gemm_smem>>>(nullptr, W_proj, b_proj, out);
}